// round 4
// baseline (speedup 1.0000x reference)
#include <cuda_runtime.h>
#include <cuda_fp16.h>
#include <math.h>

#define BB 512
#define SS 512
#define VV 50000
#define DD 300
#define PP 3
#define D4 75     // DD/4
#define KK 640    // padded concat K: [am 0..299 |pad| x 320..619 |pad]
#define NN 320    // padded output dim
#define XOFF 320  // x-region offset inside concat row
#define NSPLIT 4

// ---------------- scratch (device globals; statically zero-initialized) ------
__device__ __align__(16) float g_xcA[BB * KK];        // [am | x] buffer A
__device__ __align__(16) float g_xcB[BB * KK];        // [am | x] buffer B
__device__ __align__(16) float g_part[NSPLIT][BB * NN];
__device__ __align__(16) uint2 g_embh[(size_t)VV * D4];  // fp16 emb shadow
__device__ float g_sv[VV];               // emb[i] . v (fp16-sourced)
__device__ int   g_lens[BB];
__device__ __align__(16) float g_v[DD];  // Wk^T wk
__device__ __align__(16) float g_u2[NN]; // Wx^T (Wq^T wq), zero-padded
__device__ float g_ck, g_c2;
__device__ __align__(16) float g_Wcat[NN * KK];  // rows 0..299: [Wc |pad| Wx |pad]; rest zero
__device__ __align__(16) float g_bc[NN];         // bp + Wp bk + bx (pad zero)

// =====================================================================
// SETUP mega-kernel, 128 threads/block:
//   blocks [0,75):    Wc = Wp@Wk rows, Wx copy, bc
//   block  75:        v, u, u2, ck, c2
//   blocks [76,588):  lens + aspect mean -> xcA x-region
//   blocks [588,...): fp32 -> fp16 emb shadow (4 rows/block)
// =====================================================================
__global__ void k_setup(const float* __restrict__ Wp, const float* __restrict__ Wk,
                        const float* __restrict__ bk, const float* __restrict__ bp,
                        const float* __restrict__ bx, const float* __restrict__ Wx,
                        const float* __restrict__ Wq, const float* __restrict__ wmlp,
                        const float* __restrict__ bq,
                        const int* __restrict__ text, const int* __restrict__ asp,
                        const float* __restrict__ emb) {
    __shared__ float sf[1200];
    __shared__ float sr[8];
    __shared__ int   si[12];
    int blk = blockIdx.x, tid = threadIdx.x;

    if (blk < 75) {
        // ---- Wc rows p0..p0+3, Wx copy, bc ----
        int p0 = blk * 4;
        for (int i = tid; i < 4 * DD; i += 128) sf[i] = Wp[p0 * DD + i];
        __syncthreads();
        for (int d = tid; d < DD; d += 128) {
            float a0 = 0.f, a1 = 0.f, a2 = 0.f, a3 = 0.f;
            for (int e = 0; e < DD; e++) {
                float wk = Wk[e * DD + d];
                a0 += sf[0 * DD + e] * wk;
                a1 += sf[1 * DD + e] * wk;
                a2 += sf[2 * DD + e] * wk;
                a3 += sf[3 * DD + e] * wk;
            }
            g_Wcat[(p0 + 0) * KK + d] = a0;
            g_Wcat[(p0 + 1) * KK + d] = a1;
            g_Wcat[(p0 + 2) * KK + d] = a2;
            g_Wcat[(p0 + 3) * KK + d] = a3;
        }
        for (int i = tid; i < 4 * DD; i += 128) {
            int r = i / DD, c = i - r * DD;
            g_Wcat[(p0 + r) * KK + XOFF + c] = Wx[(p0 + r) * DD + c];
        }
        if (tid < 4) {
            float s = bp[p0 + tid] + bx[p0 + tid];
            for (int e = 0; e < DD; e++) s += sf[tid * DD + e] * bk[e];
            g_bc[p0 + tid] = s;
        }
    } else if (blk == 75) {
        // ---- v, u (in smem), then u2 = Wx^T u, and scalars ----
        for (int d = tid; d < DD; d += 128) {
            float sv = 0.f, su = 0.f;
            for (int e = 0; e < DD; e++) {
                sv += Wk[e * DD + d] * wmlp[e];
                su += Wq[e * DD + d] * wmlp[DD + e];
            }
            g_v[d] = sv;
            sf[d] = su;
        }
        __syncthreads();
        for (int d = tid; d < DD; d += 128) {
            float s = 0.f;
            for (int e = 0; e < DD; e++) s += Wx[e * DD + d] * sf[e];
            g_u2[d] = s;
        }
        float ck = 0.f, c2 = 0.f;
        for (int e = tid; e < DD; e += 128) {
            ck += bk[e] * wmlp[e];
            c2 += bq[e] * wmlp[DD + e] + bx[e] * sf[e];
        }
#pragma unroll
        for (int o = 16; o; o >>= 1) {
            ck += __shfl_xor_sync(0xffffffffu, ck, o);
            c2 += __shfl_xor_sync(0xffffffffu, c2, o);
        }
        if ((tid & 31) == 0) { sr[(tid >> 5) * 2] = ck; sr[(tid >> 5) * 2 + 1] = c2; }
        __syncthreads();
        if (tid == 0) {
            g_ck = sr[0] + sr[2] + sr[4] + sr[6];
            g_c2 = sr[1] + sr[3] + sr[5] + sr[7];
        }
    } else if (blk < 588) {
        // ---- lens + aspect mean for batch row b ----
        int b = blk - 76;
        if (tid < 8) si[tid] = asp[b * 8 + tid];
        int cnt = 0;
        for (int s = tid; s < SS; s += 128) cnt += (text[b * SS + s] != 0);
#pragma unroll
        for (int o = 16; o; o >>= 1) cnt += __shfl_xor_sync(0xffffffffu, cnt, o);
        if ((tid & 31) == 0) si[8 + (tid >> 5)] = cnt;
        __syncthreads();
        if (tid == 0) {
            g_lens[b] = si[8] + si[9] + si[10] + si[11];
            int na = 0;
            for (int a = 0; a < 8; a++) na += (si[a] != 0);
            sr[0] = 1.0f / (float)na;
        }
        __syncthreads();
        float invn = sr[0];
        for (int d = tid; d < DD; d += 128) {
            float ssum = 0.f;
#pragma unroll
            for (int a = 0; a < 8; a++) ssum += emb[(size_t)si[a] * DD + d];  // emb[0]==0
            g_xcA[b * KK + XOFF + d] = ssum * invn;
        }
    } else {
        // ---- fp16 shadow: 4 vocab rows per block ----
        int row = (blk - 588) * 4 + (tid >> 5);
        int lane = tid & 31;
        if (row < VV) {
            const float4* er = reinterpret_cast<const float4*>(emb + (size_t)row * DD);
#pragma unroll
            for (int i = lane; i < D4; i += 32) {
                float4 e = er[i];
                __half2 h0 = __floats2half2_rn(e.x, e.y);
                __half2 h1 = __floats2half2_rn(e.z, e.w);
                uint2 u;
                u.x = *reinterpret_cast<unsigned*>(&h0);
                u.y = *reinterpret_cast<unsigned*>(&h1);
                g_embh[(size_t)row * D4 + i] = u;
            }
        }
    }
}

// ---------------- sv[i] = embh[i] . v  (fp16 shadow source) -----------------
__global__ void k_sv() {
    __shared__ float4 sv4[D4];
    for (int i = threadIdx.x; i < D4; i += blockDim.x)
        sv4[i] = reinterpret_cast<const float4*>(g_v)[i];
    __syncthreads();
    int row = blockIdx.x * 4 + (threadIdx.x >> 5);
    int lane = threadIdx.x & 31;
    if (row >= VV) return;
    const uint2* er = g_embh + (size_t)row * D4;
    float acc = 0.f;
#pragma unroll
    for (int i = lane; i < D4; i += 32) {
        uint2 u = er[i];
        float2 lo = __half22float2(*reinterpret_cast<__half2*>(&u.x));
        float2 hi = __half22float2(*reinterpret_cast<__half2*>(&u.y));
        float4 vv = sv4[i];
        acc += lo.x * vv.x + lo.y * vv.y + hi.x * vv.z + hi.y * vv.w;
    }
#pragma unroll
    for (int o = 16; o; o >>= 1) acc += __shfl_xor_sync(0xffffffffu, acc, o);
    if (lane == 0) g_sv[row] = acc;
}

// ---------------- per-hop: [reduce partials] + q + softmax + gather ---------
// CUR: buffer this hop writes (0=A, 1=B). FIRST: read x directly (hop 0).
template <int CUR, int FIRST>
__global__ void k_attn(const int* __restrict__ text) {
    const int NT = 384;
    float* __restrict__ xc = CUR ? g_xcB : g_xcA;
    int b = blockIdx.x, tid = threadIdx.x;
    __shared__ float s_coef[SS];
    __shared__ int   s_idx[SS];
    __shared__ float4 s_part[4][D4];
    __shared__ float s_red[12];
    __shared__ float s_bcast;

    for (int s = tid; s < SS; s += NT) s_idx[s] = text[b * SS + s];

    float qp = 0.f;
    if (FIRST) {
        for (int d = tid; d < DD; d += NT) qp += xc[b * KK + XOFF + d] * g_u2[d];
    } else {
        if (tid < 80) {
            const float4* pp0 = reinterpret_cast<const float4*>(g_part[0] + b * NN);
            const float4* pp1 = reinterpret_cast<const float4*>(g_part[1] + b * NN);
            const float4* pp2 = reinterpret_cast<const float4*>(g_part[2] + b * NN);
            const float4* pp3 = reinterpret_cast<const float4*>(g_part[3] + b * NN);
            float4 a = pp0[tid], c = pp1[tid], d2 = pp2[tid], e = pp3[tid];
            float4 bias = reinterpret_cast<const float4*>(g_bc)[tid];
            float4 r;
            r.x = (a.x + c.x) + (d2.x + e.x) + bias.x;
            r.y = (a.y + c.y) + (d2.y + e.y) + bias.y;
            r.z = (a.z + c.z) + (d2.z + e.z) + bias.z;
            r.w = (a.w + c.w) + (d2.w + e.w) + bias.w;
            reinterpret_cast<float4*>(xc + b * KK + XOFF)[tid] = r;
            float4 u = reinterpret_cast<const float4*>(g_u2)[tid];
            qp = r.x * u.x + r.y * u.y + r.z * u.z + r.w * u.w;
        }
    }
#pragma unroll
    for (int o = 16; o; o >>= 1) qp += __shfl_xor_sync(0xffffffffu, qp, o);
    if ((tid & 31) == 0) s_red[tid >> 5] = qp;
    __syncthreads();
    if (tid == 0) {
        float q = 0.f;
        for (int w = 0; w < 12; w++) q += s_red[w];
        s_bcast = q + g_c2;
    }
    __syncthreads();
    float q = s_bcast;

    int len = g_lens[b];
    int s0 = SS - len;
    float invlen = 1.0f / (float)len;
    float ckq = g_ck + q;

    float esum = 0.f;
    for (int s = s0 + tid; s < SS; s += NT) {
        float w = 1.0f - (float)(s - s0) * invlen;
        float e = expf(tanhf(w * g_sv[s_idx[s]] + ckq));
        s_coef[s] = e;
        esum += e;
    }
#pragma unroll
    for (int o = 16; o; o >>= 1) esum += __shfl_xor_sync(0xffffffffu, esum, o);
    if ((tid & 31) == 0) s_red[tid >> 5] = esum;
    __syncthreads();
    if (tid == 0) {
        float t = (float)s0 * expf(tanhf(ckq));  // padding softmax mass
        for (int w = 0; w < 12; w++) t += s_red[w];
        s_bcast = 1.0f / t;
    }
    __syncthreads();
    float inv = s_bcast;

    for (int s = s0 + tid; s < SS; s += NT) {
        float w = 1.0f - (float)(s - s0) * invlen;
        s_coef[s] *= inv * w;
    }
    __syncthreads();

    // gather (fp16, MLP 8): 4 token-groups x 75 chunks of 4 values
    if (tid < 300) {
        int grp = tid / D4;
        int ch = tid - grp * D4;
        float4 acc = make_float4(0.f, 0.f, 0.f, 0.f);
        int s = s0 + grp;
        for (; s + 28 < SS; s += 32) {
            int ix[8]; float cf[8];
#pragma unroll
            for (int j = 0; j < 8; j++) { ix[j] = s_idx[s + 4 * j]; cf[j] = s_coef[s + 4 * j]; }
            uint2 v[8];
#pragma unroll
            for (int j = 0; j < 8; j++) v[j] = g_embh[(size_t)ix[j] * D4 + ch];
#pragma unroll
            for (int j = 0; j < 8; j++) {
                float2 lo = __half22float2(*reinterpret_cast<__half2*>(&v[j].x));
                float2 hi = __half22float2(*reinterpret_cast<__half2*>(&v[j].y));
                acc.x += cf[j] * lo.x; acc.y += cf[j] * lo.y;
                acc.z += cf[j] * hi.x; acc.w += cf[j] * hi.y;
            }
        }
        for (; s < SS; s += 4) {
            float c = s_coef[s];
            uint2 v = g_embh[(size_t)s_idx[s] * D4 + ch];
            float2 lo = __half22float2(*reinterpret_cast<__half2*>(&v.x));
            float2 hi = __half22float2(*reinterpret_cast<__half2*>(&v.y));
            acc.x += c * lo.x; acc.y += c * lo.y;
            acc.z += c * hi.x; acc.w += c * hi.y;
        }
        s_part[grp][ch] = acc;
    }
    __syncthreads();
    if (tid < D4) {
        float4 a0 = s_part[0][tid], a1 = s_part[1][tid];
        float4 a2 = s_part[2][tid], a3 = s_part[3][tid];
        float4 r;
        r.x = (a0.x + a1.x) + (a2.x + a3.x);
        r.y = (a0.y + a1.y) + (a2.y + a3.y);
        r.z = (a0.z + a1.z) + (a2.z + a3.z);
        r.w = (a0.w + a1.w) + (a2.w + a3.w);
        reinterpret_cast<float4*>(xc + b * KK)[tid] = r;   // am region
    }
}

// ---------------- tiled GEMM: part[sk] = Xcur[:, k0:k0+160] @ Wcat[...]^T ----
#define SROW 68
template <int CUR>
__global__ __launch_bounds__(256, 2) void k_gemm() {
    const float* __restrict__ xc = CUR ? g_xcB : g_xcA;
    __shared__ float Xs[2][16 * SROW];
    __shared__ float Ws[2][16 * SROW];
    int b0 = blockIdx.x * 64, d0 = blockIdx.y * 64, sk = blockIdx.z;
    int k0 = sk * 160;
    const int nt = 10;
    int tid = threadIdx.x;
    int lr = tid >> 2, lk = (tid & 3) << 2;
    int rt = tid >> 4, ct = tid & 15;

    float acc[4][4] = {};
    float4 rx, rw;

    rx = *reinterpret_cast<const float4*>(xc + (b0 + lr) * KK + k0 + lk);
    rw = *reinterpret_cast<const float4*>(g_Wcat + (d0 + lr) * KK + k0 + lk);
    {
        float* xs = Xs[0]; float* ws = Ws[0];
        xs[(lk + 0) * SROW + lr] = rx.x; xs[(lk + 1) * SROW + lr] = rx.y;
        xs[(lk + 2) * SROW + lr] = rx.z; xs[(lk + 3) * SROW + lr] = rx.w;
        ws[(lk + 0) * SROW + lr] = rw.x; ws[(lk + 1) * SROW + lr] = rw.y;
        ws[(lk + 2) * SROW + lr] = rw.z; ws[(lk + 3) * SROW + lr] = rw.w;
    }
    __syncthreads();

    for (int t = 0; t < nt; t++) {
        if (t + 1 < nt) {
            int kt = k0 + ((t + 1) << 4);
            rx = *reinterpret_cast<const float4*>(xc + (b0 + lr) * KK + kt + lk);
            rw = *reinterpret_cast<const float4*>(g_Wcat + (d0 + lr) * KK + kt + lk);
        }
        const float* xs = Xs[t & 1];
        const float* ws = Ws[t & 1];
#pragma unroll
        for (int kk = 0; kk < 16; kk++) {
            float4 xv = *reinterpret_cast<const float4*>(xs + kk * SROW + rt * 4);
            float4 wv = *reinterpret_cast<const float4*>(ws + kk * SROW + ct * 4);
            acc[0][0] += xv.x * wv.x; acc[0][1] += xv.x * wv.y; acc[0][2] += xv.x * wv.z; acc[0][3] += xv.x * wv.w;
            acc[1][0] += xv.y * wv.x; acc[1][1] += xv.y * wv.y; acc[1][2] += xv.y * wv.z; acc[1][3] += xv.y * wv.w;
            acc[2][0] += xv.z * wv.x; acc[2][1] += xv.z * wv.y; acc[2][2] += xv.z * wv.z; acc[2][3] += xv.z * wv.w;
            acc[3][0] += xv.w * wv.x; acc[3][1] += xv.w * wv.y; acc[3][2] += xv.w * wv.z; acc[3][3] += xv.w * wv.w;
        }
        __syncthreads();
        if (t + 1 < nt) {
            float* xs2 = Xs[(t + 1) & 1]; float* ws2 = Ws[(t + 1) & 1];
            xs2[(lk + 0) * SROW + lr] = rx.x; xs2[(lk + 1) * SROW + lr] = rx.y;
            xs2[(lk + 2) * SROW + lr] = rx.z; xs2[(lk + 3) * SROW + lr] = rx.w;
            ws2[(lk + 0) * SROW + lr] = rw.x; ws2[(lk + 1) * SROW + lr] = rw.y;
            ws2[(lk + 2) * SROW + lr] = rw.z; ws2[(lk + 3) * SROW + lr] = rw.w;
            __syncthreads();
        }
    }

    float* po = g_part[sk];
#pragma unroll
    for (int r = 0; r < 4; r++) {
        float4 o = make_float4(acc[r][0], acc[r][1], acc[r][2], acc[r][3]);
        *reinterpret_cast<float4*>(po + (b0 + rt * 4 + r) * NN + d0 + ct * 4) = o;
    }
}

// ---------------- final: reduce partials -> x, out = x @ Wd.T + bd ----------
__global__ void k_final(const float* __restrict__ Wd, const float* __restrict__ bd,
                        float* __restrict__ out) {
    int b = blockIdx.x, tid = threadIdx.x;   // 320 threads
    __shared__ float sx[NN];
    __shared__ float sr[10][3];
    if (tid < 80) {
        const float4* pp0 = reinterpret_cast<const float4*>(g_part[0] + b * NN);
        const float4* pp1 = reinterpret_cast<const float4*>(g_part[1] + b * NN);
        const float4* pp2 = reinterpret_cast<const float4*>(g_part[2] + b * NN);
        const float4* pp3 = reinterpret_cast<const float4*>(g_part[3] + b * NN);
        float4 a = pp0[tid], c = pp1[tid], d2 = pp2[tid], e = pp3[tid];
        float4 bias = reinterpret_cast<const float4*>(g_bc)[tid];
        float4 r;
        r.x = (a.x + c.x) + (d2.x + e.x) + bias.x;
        r.y = (a.y + c.y) + (d2.y + e.y) + bias.y;
        r.z = (a.z + c.z) + (d2.z + e.z) + bias.z;
        r.w = (a.w + c.w) + (d2.w + e.w) + bias.w;
        reinterpret_cast<float4*>(sx)[tid] = r;
    }
    __syncthreads();
    float a0 = 0.f, a1 = 0.f, a2 = 0.f;
    if (tid < DD) {
        float xv = sx[tid];
        a0 = xv * Wd[tid];
        a1 = xv * Wd[DD + tid];
        a2 = xv * Wd[2 * DD + tid];
    }
#pragma unroll
    for (int o = 16; o; o >>= 1) {
        a0 += __shfl_xor_sync(0xffffffffu, a0, o);
        a1 += __shfl_xor_sync(0xffffffffu, a1, o);
        a2 += __shfl_xor_sync(0xffffffffu, a2, o);
    }
    if ((tid & 31) == 0) { int w = tid >> 5; sr[w][0] = a0; sr[w][1] = a1; sr[w][2] = a2; }
    __syncthreads();
    if (tid == 0) {
        float r0 = bd[0], r1 = bd[1], r2 = bd[2];
        for (int w = 0; w < 10; w++) { r0 += sr[w][0]; r1 += sr[w][1]; r2 += sr[w][2]; }
        out[b * PP + 0] = r0;
        out[b * PP + 1] = r1;
        out[b * PP + 2] = r2;
    }
}

// ---------------- launch -----------------
extern "C" void kernel_launch(void* const* d_in, const int* in_sizes, int n_in,
                              void* d_out, int out_size) {
    const int*   text = (const int*)d_in[0];
    const int*   asp  = (const int*)d_in[1];
    const float* emb  = (const float*)d_in[2];
    const float* Wx   = (const float*)d_in[3];
    const float* bx   = (const float*)d_in[4];
    const float* Wk   = (const float*)d_in[5];
    const float* bk   = (const float*)d_in[6];
    const float* Wq   = (const float*)d_in[7];
    const float* bq   = (const float*)d_in[8];
    const float* wmlp = (const float*)d_in[9];
    const float* Wp   = (const float*)d_in[10];
    const float* bp   = (const float*)d_in[11];
    const float* Wd   = (const float*)d_in[12];
    const float* bd   = (const float*)d_in[13];
    float* out = (float*)d_out;

    k_setup<<<588 + 12500, 128>>>(Wp, Wk, bk, bp, bx, Wx, Wq, wmlp, bq, text, asp, emb);
    k_sv<<<12500, 128>>>();

    dim3 gg(8, 5, NSPLIT);
    k_attn<0, 1><<<BB, 384>>>(text);   // hop 0: x from xcA
    k_gemm<0><<<gg, 256>>>();
    k_attn<1, 0><<<BB, 384>>>(text);   // hop 1: reduce -> xcB
    k_gemm<1><<<gg, 256>>>();
    k_attn<0, 0><<<BB, 384>>>(text);   // hop 2: reduce -> xcA
    k_gemm<0><<<gg, 256>>>();

    k_final<<<BB, 320>>>(Wd, bd, out);
}

// round 5
// speedup vs baseline: 1.2460x; 1.2460x over previous
#include <cuda_runtime.h>
#include <cuda_fp16.h>
#include <math.h>

#define BB 512
#define SS 512
#define VV 50000
#define DD 300
#define PP 3
#define D4 75     // DD/4
#define KK 640    // padded concat K: [am 0..299 |pad| x 320..619 |pad]
#define NN 320    // padded output dim
#define XOFF 320  // x-region offset inside concat row
#define NSPLIT 4

// ---------------- scratch (device globals; statically zero-initialized) ------
__device__ __align__(16) float g_xcA[BB * KK];   // [am | x] buffer A
__device__ __align__(16) float g_xcB[BB * KK];   // [am | x] buffer B
__device__ __align__(16) float g_part[NSPLIT][BB * NN]; // splitK partials
__device__ __align__(16) uint2 g_embh[(size_t)VV * D4]; // fp16 emb shadow
__device__ float g_sv[VV];               // emb[i] . v
__device__ int   g_lens[BB];
__device__ __align__(16) float g_v[DD];  // Wk^T wk
__device__ float g_u[DD];                // Wq^T wq
__device__ float g_u2[DD];               // Wx^T u
__device__ float g_ck, g_cq, g_c2;
__device__ __align__(16) float g_Wcat[NN * KK];  // rows 0..299: [Wc |pad| Wx |pad]; rest zero
__device__ __align__(16) float g_bc[NN];         // bp + Wp bk + bx (pad zero)

// ---------------- prep1: v, u, ck, cq (one warp per d) -----------------
__global__ void k_prep1(const float* __restrict__ Wk, const float* __restrict__ Wq,
                        const float* __restrict__ wmlp, const float* __restrict__ bk,
                        const float* __restrict__ bq) {
    int w = (blockIdx.x * blockDim.x + threadIdx.x) >> 5;
    int lane = threadIdx.x & 31;
    if (w < DD) {
        float sv = 0.f, su = 0.f;
        for (int e = lane; e < DD; e += 32) {
            sv += Wk[e * DD + w] * wmlp[e];
            su += Wq[e * DD + w] * wmlp[DD + e];
        }
#pragma unroll
        for (int o = 16; o; o >>= 1) {
            sv += __shfl_xor_sync(0xffffffffu, sv, o);
            su += __shfl_xor_sync(0xffffffffu, su, o);
        }
        if (lane == 0) { g_v[w] = sv; g_u[w] = su; }
    } else if (w == DD) {
        float ck = 0.f, cq = 0.f;
        for (int e = lane; e < DD; e += 32) {
            ck += bk[e] * wmlp[e];
            cq += bq[e] * wmlp[DD + e];
        }
#pragma unroll
        for (int o = 16; o; o >>= 1) {
            ck += __shfl_xor_sync(0xffffffffu, ck, o);
            cq += __shfl_xor_sync(0xffffffffu, cq, o);
        }
        if (lane == 0) { g_ck = ck; g_cq = cq; }
    }
}

// ---------------- prep2: u2 = Wx^T u, c2 (one warp per d) -----------------
__global__ void k_prep2(const float* __restrict__ Wx, const float* __restrict__ bx) {
    int w = (blockIdx.x * blockDim.x + threadIdx.x) >> 5;
    int lane = threadIdx.x & 31;
    if (w < DD) {
        float s = 0.f;
        for (int e = lane; e < DD; e += 32) s += Wx[e * DD + w] * g_u[e];
#pragma unroll
        for (int o = 16; o; o >>= 1) s += __shfl_xor_sync(0xffffffffu, s, o);
        if (lane == 0) g_u2[w] = s;
    } else if (w == DD) {
        float c = 0.f;
        for (int e = lane; e < DD; e += 32) c += bx[e] * g_u[e];
#pragma unroll
        for (int o = 16; o; o >>= 1) c += __shfl_xor_sync(0xffffffffu, c, o);
        if (lane == 0) g_c2 = c + g_cq;
    }
}

// ---------------- prep_W: Wcat rows (Wc = Wp@Wk, copy Wx), bc ----------
__global__ void k_prep_W(const float* __restrict__ Wp, const float* __restrict__ Wk,
                         const float* __restrict__ bk, const float* __restrict__ bp,
                         const float* __restrict__ bx, const float* __restrict__ Wx) {
    int p0 = blockIdx.x * 4;
    int tid = threadIdx.x;
    __shared__ float srow[4 * DD];
    for (int i = tid; i < 4 * DD; i += blockDim.x) srow[i] = Wp[p0 * DD + i];
    __syncthreads();
    for (int d = tid; d < DD; d += blockDim.x) {
        float a0 = 0.f, a1 = 0.f, a2 = 0.f, a3 = 0.f;
        for (int e = 0; e < DD; e++) {
            float wk = Wk[e * DD + d];
            a0 += srow[0 * DD + e] * wk;
            a1 += srow[1 * DD + e] * wk;
            a2 += srow[2 * DD + e] * wk;
            a3 += srow[3 * DD + e] * wk;
        }
        g_Wcat[(p0 + 0) * KK + d] = a0;
        g_Wcat[(p0 + 1) * KK + d] = a1;
        g_Wcat[(p0 + 2) * KK + d] = a2;
        g_Wcat[(p0 + 3) * KK + d] = a3;
    }
    for (int i = tid; i < 4 * DD; i += blockDim.x) {
        int r = i / DD, c = i - r * DD;
        g_Wcat[(p0 + r) * KK + XOFF + c] = Wx[(p0 + r) * DD + c];
    }
    if (tid < 4) {
        float s = bp[p0 + tid] + bx[p0 + tid];
        for (int e = 0; e < DD; e++) s += srow[tid * DD + e] * bk[e];
        g_bc[p0 + tid] = s;
    }
}

// ---------------- vocab: sv[i] = emb[i].v  +  fp16 shadow -----------------
__global__ void k_vocab(const float* __restrict__ emb) {
    __shared__ float4 sv4[D4];
    for (int i = threadIdx.x; i < D4; i += blockDim.x)
        sv4[i] = reinterpret_cast<const float4*>(g_v)[i];
    __syncthreads();
    int row = blockIdx.x * 4 + (threadIdx.x >> 5);
    int lane = threadIdx.x & 31;
    if (row >= VV) return;
    const float4* er = reinterpret_cast<const float4*>(emb + (size_t)row * DD);
    float acc = 0.f;
#pragma unroll
    for (int i = lane; i < D4; i += 32) {
        float4 e = er[i];
        float4 vv = sv4[i];
        acc += e.x * vv.x + e.y * vv.y + e.z * vv.z + e.w * vv.w;
        __half2 h0 = __floats2half2_rn(e.x, e.y);
        __half2 h1 = __floats2half2_rn(e.z, e.w);
        uint2 u;
        u.x = *reinterpret_cast<unsigned*>(&h0);
        u.y = *reinterpret_cast<unsigned*>(&h1);
        g_embh[(size_t)row * D4 + i] = u;
    }
#pragma unroll
    for (int o = 16; o; o >>= 1) acc += __shfl_xor_sync(0xffffffffu, acc, o);
    if (lane == 0) g_sv[row] = acc;
}

// ---------------- lens + aspect mean (x into buffer A) -----------------
__global__ void k_lens_aspect(const int* __restrict__ text, const int* __restrict__ asp,
                              const float* __restrict__ emb) {
    int b = blockIdx.x, tid = threadIdx.x;
    __shared__ int s_asp[8];
    __shared__ int s_red[4];
    __shared__ float s_invn;
    if (tid < 8) s_asp[tid] = asp[b * 8 + tid];
    int cnt = 0;
    for (int s = tid; s < SS; s += 128) cnt += (text[b * SS + s] != 0);
#pragma unroll
    for (int o = 16; o; o >>= 1) cnt += __shfl_xor_sync(0xffffffffu, cnt, o);
    if ((tid & 31) == 0) s_red[tid >> 5] = cnt;
    __syncthreads();
    if (tid == 0) {
        g_lens[b] = s_red[0] + s_red[1] + s_red[2] + s_red[3];
        int na = 0;
        for (int a = 0; a < 8; a++) na += (s_asp[a] != 0);
        s_invn = 1.0f / (float)na;
    }
    __syncthreads();
    float invn = s_invn;
    for (int d = tid; d < DD; d += 128) {
        float ssum = 0.f;
#pragma unroll
        for (int a = 0; a < 8; a++) ssum += emb[(size_t)s_asp[a] * DD + d];  // emb[0]==0
        g_xcA[b * KK + XOFF + d] = ssum * invn;
    }
}

// ---------------- per-hop: q + softmax + fp16 weighted gather --------------
template <int CUR>
__global__ void k_attn(const int* __restrict__ text) {
    const int NT = 384;
    float* __restrict__ xc = CUR ? g_xcB : g_xcA;
    int b = blockIdx.x, tid = threadIdx.x;
    __shared__ float s_coef[SS];
    __shared__ int   s_idx[SS];
    __shared__ float4 s_part[4][D4];
    __shared__ float s_red[12];
    __shared__ float s_bcast;

    for (int s = tid; s < SS; s += NT) s_idx[s] = text[b * SS + s];

    float qp = 0.f;
    for (int d = tid; d < DD; d += NT) qp += xc[b * KK + XOFF + d] * g_u2[d];
#pragma unroll
    for (int o = 16; o; o >>= 1) qp += __shfl_xor_sync(0xffffffffu, qp, o);
    if ((tid & 31) == 0) s_red[tid >> 5] = qp;
    __syncthreads();
    if (tid == 0) {
        float q = 0.f;
        for (int w = 0; w < 12; w++) q += s_red[w];
        s_bcast = q + g_c2;
    }
    __syncthreads();
    float q = s_bcast;

    int len = g_lens[b];
    int s0 = SS - len;
    float invlen = 1.0f / (float)len;
    float ckq = g_ck + q;

    float esum = 0.f;
    for (int s = s0 + tid; s < SS; s += NT) {
        float w = 1.0f - (float)(s - s0) * invlen;
        float e = expf(tanhf(w * g_sv[s_idx[s]] + ckq));
        s_coef[s] = e;
        esum += e;
    }
#pragma unroll
    for (int o = 16; o; o >>= 1) esum += __shfl_xor_sync(0xffffffffu, esum, o);
    if ((tid & 31) == 0) s_red[tid >> 5] = esum;
    __syncthreads();
    if (tid == 0) {
        float t = (float)s0 * expf(tanhf(ckq));  // padding softmax mass
        for (int w = 0; w < 12; w++) t += s_red[w];
        s_bcast = 1.0f / t;
    }
    __syncthreads();
    float inv = s_bcast;

    for (int s = s0 + tid; s < SS; s += NT) {
        float w = 1.0f - (float)(s - s0) * invlen;
        s_coef[s] *= inv * w;
    }
    __syncthreads();

    // gather (fp16, MLP 8): 4 token-groups x 75 chunks of 4 values
    if (tid < 300) {
        int grp = tid / D4;
        int ch = tid - grp * D4;
        float4 acc = make_float4(0.f, 0.f, 0.f, 0.f);
        int s = s0 + grp;
        for (; s + 28 < SS; s += 32) {
            int ix[8]; float cf[8];
#pragma unroll
            for (int j = 0; j < 8; j++) { ix[j] = s_idx[s + 4 * j]; cf[j] = s_coef[s + 4 * j]; }
            uint2 v[8];
#pragma unroll
            for (int j = 0; j < 8; j++) v[j] = g_embh[(size_t)ix[j] * D4 + ch];
#pragma unroll
            for (int j = 0; j < 8; j++) {
                float2 lo = __half22float2(*reinterpret_cast<__half2*>(&v[j].x));
                float2 hi = __half22float2(*reinterpret_cast<__half2*>(&v[j].y));
                acc.x += cf[j] * lo.x; acc.y += cf[j] * lo.y;
                acc.z += cf[j] * hi.x; acc.w += cf[j] * hi.y;
            }
        }
        for (; s < SS; s += 4) {
            float c = s_coef[s];
            uint2 v = g_embh[(size_t)s_idx[s] * D4 + ch];
            float2 lo = __half22float2(*reinterpret_cast<__half2*>(&v.x));
            float2 hi = __half22float2(*reinterpret_cast<__half2*>(&v.y));
            acc.x += c * lo.x; acc.y += c * lo.y;
            acc.z += c * hi.x; acc.w += c * hi.y;
        }
        s_part[grp][ch] = acc;
    }
    __syncthreads();
    if (tid < D4) {
        float4 a0 = s_part[0][tid], a1 = s_part[1][tid];
        float4 a2 = s_part[2][tid], a3 = s_part[3][tid];
        float4 r;
        r.x = (a0.x + a1.x) + (a2.x + a3.x);
        r.y = (a0.y + a1.y) + (a2.y + a3.y);
        r.z = (a0.z + a1.z) + (a2.z + a3.z);
        r.w = (a0.w + a1.w) + (a2.w + a3.w);
        reinterpret_cast<float4*>(xc + b * KK)[tid] = r;   // am region
    }
}

// ---------------- GEMM: part[sk] = Xcur[:, k0:k0+160] @ Wcat[:, k0:k0+160]^T
// BM=64 BN=32 BK=32, 256 threads, 4x2 thread tiles, single-buffer smem.
// grid (8, 10, 4) = 320 blocks -> 2+ CTAs/SM, barriers overlap across CTAs.
#define GXR 68   // BM + 4 pad (272B rows, 16B-aligned)
#define GWR 36   // BN + 4 pad (144B rows, 16B-aligned)
template <int CUR>
__global__ __launch_bounds__(256) void k_gemm() {
    const float* __restrict__ xc = CUR ? g_xcB : g_xcA;
    __shared__ float Xs[32 * GXR];   // [k][m]
    __shared__ float Ws[32 * GWR];   // [k][n]
    int b0 = blockIdx.x * 64, d0 = blockIdx.y * 32;
    int k0 = blockIdx.z * 160;
    int tid = threadIdx.x;

    // load mappings
    int xlr = tid >> 2, xlc = tid & 3;        // X: row 0..63, float4-col 0..3 (+4)
    int wlr = tid >> 3, wlc = tid & 7;        // W: row 0..31, float4-col 0..7
    // compute mapping: 16x16 thread grid, 4 rows x 2 cols each
    int tm = (tid >> 4) << 2, tn = (tid & 15) << 1;

    float acc[4][2] = {};

#pragma unroll 1
    for (int t = 0; t < 5; t++) {
        int kt = k0 + t * 32;
        float4 x0 = *reinterpret_cast<const float4*>(xc + (b0 + xlr) * KK + kt + xlc * 4);
        float4 x1 = *reinterpret_cast<const float4*>(xc + (b0 + xlr) * KK + kt + (xlc + 4) * 4);
        float4 w0 = *reinterpret_cast<const float4*>(g_Wcat + (d0 + wlr) * KK + kt + wlc * 4);
        __syncthreads();
        Xs[(xlc * 4 + 0) * GXR + xlr] = x0.x;
        Xs[(xlc * 4 + 1) * GXR + xlr] = x0.y;
        Xs[(xlc * 4 + 2) * GXR + xlr] = x0.z;
        Xs[(xlc * 4 + 3) * GXR + xlr] = x0.w;
        Xs[((xlc + 4) * 4 + 0) * GXR + xlr] = x1.x;
        Xs[((xlc + 4) * 4 + 1) * GXR + xlr] = x1.y;
        Xs[((xlc + 4) * 4 + 2) * GXR + xlr] = x1.z;
        Xs[((xlc + 4) * 4 + 3) * GXR + xlr] = x1.w;
        Ws[(wlc * 4 + 0) * GWR + wlr] = w0.x;
        Ws[(wlc * 4 + 1) * GWR + wlr] = w0.y;
        Ws[(wlc * 4 + 2) * GWR + wlr] = w0.z;
        Ws[(wlc * 4 + 3) * GWR + wlr] = w0.w;
        __syncthreads();
#pragma unroll
        for (int kk = 0; kk < 32; kk++) {
            float4 xv = *reinterpret_cast<const float4*>(Xs + kk * GXR + tm);
            float2 wv = *reinterpret_cast<const float2*>(Ws + kk * GWR + tn);
            acc[0][0] += xv.x * wv.x; acc[0][1] += xv.x * wv.y;
            acc[1][0] += xv.y * wv.x; acc[1][1] += xv.y * wv.y;
            acc[2][0] += xv.z * wv.x; acc[2][1] += xv.z * wv.y;
            acc[3][0] += xv.w * wv.x; acc[3][1] += xv.w * wv.y;
        }
    }

    float* po = g_part[blockIdx.z];
#pragma unroll
    for (int r = 0; r < 4; r++) {
        float2 o = make_float2(acc[r][0], acc[r][1]);
        *reinterpret_cast<float2*>(po + (b0 + tm + r) * NN + d0 + tn) = o;
    }
}

// ---------------- reduce partials + bias -> next x -----------------
template <int NXT>
__global__ void k_reduce() {
    float* __restrict__ xn = NXT ? g_xcB : g_xcA;
    int idx = blockIdx.x * blockDim.x + threadIdx.x;   // 0 .. 512*80-1 (float4)
    int b = idx / 80, d4 = idx - b * 80;
    const float4* p0 = reinterpret_cast<const float4*>(g_part[0]);
    const float4* p1 = reinterpret_cast<const float4*>(g_part[1]);
    const float4* p2 = reinterpret_cast<const float4*>(g_part[2]);
    const float4* p3 = reinterpret_cast<const float4*>(g_part[3]);
    float4 a = p0[idx], c = p1[idx], e = p2[idx], f = p3[idx];
    float4 bias = reinterpret_cast<const float4*>(g_bc)[d4];
    float4 r;
    r.x = (a.x + c.x) + (e.x + f.x) + bias.x;
    r.y = (a.y + c.y) + (e.y + f.y) + bias.y;
    r.z = (a.z + c.z) + (e.z + f.z) + bias.z;
    r.w = (a.w + c.w) + (e.w + f.w) + bias.w;
    reinterpret_cast<float4*>(xn + b * KK + XOFF)[d4] = r;
}

// ---------------- final: out = x @ Wd.T + bd ----------
template <int XBUF>
__global__ void k_final(const float* __restrict__ Wd, const float* __restrict__ bd,
                        float* __restrict__ out) {
    const float* __restrict__ xc = XBUF ? g_xcB : g_xcA;
    int wid = (blockIdx.x * blockDim.x + threadIdx.x) >> 5;
    int lane = threadIdx.x & 31;
    if (wid >= BB) return;
    float a0 = 0.f, a1 = 0.f, a2 = 0.f;
    for (int k = lane; k < DD; k += 32) {
        float xv = xc[wid * KK + XOFF + k];
        a0 += xv * Wd[0 * DD + k];
        a1 += xv * Wd[1 * DD + k];
        a2 += xv * Wd[2 * DD + k];
    }
#pragma unroll
    for (int o = 16; o; o >>= 1) {
        a0 += __shfl_xor_sync(0xffffffffu, a0, o);
        a1 += __shfl_xor_sync(0xffffffffu, a1, o);
        a2 += __shfl_xor_sync(0xffffffffu, a2, o);
    }
    if (lane == 0) {
        out[wid * PP + 0] = a0 + bd[0];
        out[wid * PP + 1] = a1 + bd[1];
        out[wid * PP + 2] = a2 + bd[2];
    }
}

// ---------------- launch -----------------
extern "C" void kernel_launch(void* const* d_in, const int* in_sizes, int n_in,
                              void* d_out, int out_size) {
    const int*   text = (const int*)d_in[0];
    const int*   asp  = (const int*)d_in[1];
    const float* emb  = (const float*)d_in[2];
    const float* Wx   = (const float*)d_in[3];
    const float* bx   = (const float*)d_in[4];
    const float* Wk   = (const float*)d_in[5];
    const float* bk   = (const float*)d_in[6];
    const float* Wq   = (const float*)d_in[7];
    const float* bq   = (const float*)d_in[8];
    const float* wmlp = (const float*)d_in[9];
    const float* Wp   = (const float*)d_in[10];
    const float* bp   = (const float*)d_in[11];
    const float* Wd   = (const float*)d_in[12];
    const float* bd   = (const float*)d_in[13];
    float* out = (float*)d_out;

    k_prep1<<<38, 256>>>(Wk, Wq, wmlp, bk, bq);
    k_prep2<<<38, 256>>>(Wx, bx);
    k_prep_W<<<75, 128>>>(Wp, Wk, bk, bp, bx, Wx);
    k_vocab<<<(VV + 3) / 4, 128>>>(emb);
    k_lens_aspect<<<BB, 128>>>(text, asp, emb);

    dim3 gg(8, 10, NSPLIT);
    // hop 0: A -> B
    k_attn<0><<<BB, 384>>>(text);
    k_gemm<0><<<gg, 256>>>();
    k_reduce<1><<<160, 256>>>();
    // hop 1: B -> A
    k_attn<1><<<BB, 384>>>(text);
    k_gemm<1><<<gg, 256>>>();
    k_reduce<0><<<160, 256>>>();
    // hop 2: A -> B
    k_attn<0><<<BB, 384>>>(text);
    k_gemm<0><<<gg, 256>>>();
    k_reduce<1><<<160, 256>>>();

    k_final<1><<<64, 256>>>(Wd, bd, out);
}

// round 6
// speedup vs baseline: 2.2284x; 1.7885x over previous
#include <cuda_runtime.h>
#include <cuda_fp16.h>
#include <math.h>

#define BB 512
#define SS 512
#define VV 50000
#define DD 300
#define PP 3
#define D4 75   // DD/4

// ---------------- scratch (device globals) ----------------
__device__ float g_u[DD], g_v[DD], g_u2[DD], g_b1[DD], g_b2[DD];
__device__ float g_p1[DD], g_p2[DD], g_a1v[DD], g_a2v[DD], g_bcv[DD];
__device__ float g_G[PP * DD], g_E[PP * DD], g_H[PP * DD], g_F[PP * DD], g_J[PP * DD];
__device__ float g_M2[PP * DD], g_M1[PP * DD], g_M0[PP * DD], g_Mx[PP * DD];
__device__ float g_ck, g_cq, g_c2, g_cc1, g_cc2;
__device__ float g_cvec[PP];
__device__ __align__(16) float4 g_svt[VV];              // {sv, t1, t2, 0} per vocab id
__device__ __align__(16) uint2 g_embh[(size_t)VV * D4]; // fp16 emb shadow
__device__ float g_x0[BB * DD];
__device__ int   g_lens[BB];

// ---------------- prep helpers ----------------
// col-dot: out[f] = sum_e M[e,f] * y[e]   (thread-per-f, coalesced)
__device__ __forceinline__ void coldot(const float* __restrict__ M,
                                       const float* __restrict__ y,
                                       float* __restrict__ out, int t) {
    if (t < DD) {
        float s = 0.f;
        for (int e = 0; e < DD; e++) s += M[e * DD + t] * y[e];
        out[t] = s;
    }
}
// matmat row: out[f] = sum_e Arow[e] * B[e,f]   (thread-per-f)
__device__ __forceinline__ void matrow(const float* __restrict__ Arow,
                                       const float* __restrict__ B,
                                       float* __restrict__ outrow, int t) {
    if (t < DD) {
        float s = 0.f;
        for (int e = 0; e < DD; e++) s += Arow[e] * B[e * DD + t];
        outrow[t] = s;
    }
}
// warp lane-dot over DD
__device__ __forceinline__ float lanedot(const float* __restrict__ a,
                                         const float* __restrict__ b, int lane) {
    float s = 0.f;
    for (int e = lane; e < DD; e += 32) s += a[e] * b[e];
#pragma unroll
    for (int o = 16; o; o >>= 1) s += __shfl_xor_sync(0xffffffffu, s, o);
    return s;
}

// ---------------- level 1 ----------------
// u = Wq^T wq, v = Wk^T wk, ck, cq, bc = Wp@bk + bp + bx, G = Wd@Wp, E = Wd@Wx
__global__ void k_lvl1(const float* __restrict__ Wq, const float* __restrict__ Wk,
                       const float* __restrict__ Wp, const float* __restrict__ Wx,
                       const float* __restrict__ Wd, const float* __restrict__ wmlp,
                       const float* __restrict__ bk, const float* __restrict__ bq,
                       const float* __restrict__ bp, const float* __restrict__ bx) {
    int b = blockIdx.x, t = threadIdx.x;   // 320 threads
    int lane = t & 31, wid = t >> 5;
    if (b == 0) {
        coldot(Wq, wmlp + DD, g_u, t);
    } else if (b == 1) {
        coldot(Wk, wmlp, g_v, t);
    } else if (b == 2) {
        if (wid == 0) { float s = lanedot(bk, wmlp, lane); if (lane == 0) g_ck = s; }
        if (wid == 1) { float s = lanedot(bq, wmlp + DD, lane); if (lane == 0) g_cq = s; }
    } else if (b < 33) {
        int d = (b - 3) * 10 + wid;   // 30 blocks x 10 warps = 300
        if (d < DD) {
            float s = lanedot(Wp + d * DD, bk, lane);
            if (lane == 0) g_bcv[d] = s + bp[d] + bx[d];
        }
    } else if (b < 36) {
        int p = b - 33;
        matrow(Wd + p * DD, Wp, g_G + p * DD, t);
    } else {
        int p = b - 36;
        matrow(Wd + p * DD, Wx, g_E + p * DD, t);
    }
}

// ---------------- level 2 ----------------
// u2 = Wx^T u, c2 = bx.u + cq, M2 = G@Wk, H = E@Wp, F = E@Wx
__global__ void k_lvl2(const float* __restrict__ Wk, const float* __restrict__ Wp,
                       const float* __restrict__ Wx, const float* __restrict__ bx) {
    int b = blockIdx.x, t = threadIdx.x;
    int lane = t & 31, wid = t >> 5;
    if (b == 0) {
        coldot(Wx, g_u, g_u2, t);
    } else if (b == 1) {
        if (wid == 0) { float s = lanedot(bx, g_u, lane); if (lane == 0) g_c2 = s + g_cq; }
    } else if (b < 5) {
        int p = b - 2;
        matrow(g_G + p * DD, Wk, g_M2 + p * DD, t);
    } else if (b < 8) {
        int p = b - 5;
        matrow(g_E + p * DD, Wp, g_H + p * DD, t);
    } else {
        int p = b - 8;
        matrow(g_E + p * DD, Wx, g_F + p * DD, t);
    }
}

// ---------------- level 3 ----------------
// b1 = Wx^T u2, p1 = Wp^T u2, cc1 = bc.u2 + c2, M1 = H@Wk, Mx = F@Wx, J = F@Wp,
// cvec = bd + (Wd+E+F)@bc
__global__ void k_lvl3(const float* __restrict__ Wk, const float* __restrict__ Wp,
                       const float* __restrict__ Wx, const float* __restrict__ Wd,
                       const float* __restrict__ bd) {
    int b = blockIdx.x, t = threadIdx.x;
    int lane = t & 31, wid = t >> 5;
    if (b == 0) {
        coldot(Wx, g_u2, g_b1, t);
    } else if (b == 1) {
        coldot(Wp, g_u2, g_p1, t);
    } else if (b == 2) {
        if (wid == 0) { float s = lanedot(g_bcv, g_u2, lane); if (lane == 0) g_cc1 = s + g_c2; }
    } else if (b < 6) {
        int p = b - 3;
        matrow(g_H + p * DD, Wk, g_M1 + p * DD, t);
    } else if (b < 9) {
        int p = b - 6;
        matrow(g_F + p * DD, Wx, g_Mx + p * DD, t);
    } else if (b < 12) {
        int p = b - 9;
        matrow(g_F + p * DD, Wp, g_J + p * DD, t);
    } else {
        if (wid < PP) {
            float s = 0.f;
            for (int e = lane; e < DD; e += 32)
                s += (Wd[wid * DD + e] + g_E[wid * DD + e] + g_F[wid * DD + e]) * g_bcv[e];
#pragma unroll
            for (int o = 16; o; o >>= 1) s += __shfl_xor_sync(0xffffffffu, s, o);
            if (lane == 0) g_cvec[wid] = s + bd[wid];
        }
    }
}

// ---------------- level 4 ----------------
// a1 = Wk^T p1, b2 = Wx^T b1, p2 = Wp^T b1, cc2 = bc.b1 + cc1, M0 = J@Wk
__global__ void k_lvl4(const float* __restrict__ Wk, const float* __restrict__ Wp,
                       const float* __restrict__ Wx) {
    int b = blockIdx.x, t = threadIdx.x;
    int lane = t & 31, wid = t >> 5;
    if (b == 0) {
        coldot(Wk, g_p1, g_a1v, t);
    } else if (b == 1) {
        coldot(Wx, g_b1, g_b2, t);
    } else if (b == 2) {
        coldot(Wp, g_b1, g_p2, t);
    } else if (b == 3) {
        if (wid == 0) { float s = lanedot(g_bcv, g_b1, lane); if (lane == 0) g_cc2 = s + g_cc1; }
    } else {
        int p = b - 4;
        matrow(g_J + p * DD, Wk, g_M0 + p * DD, t);
    }
}

// ---------------- level 5: a2 = Wk^T p2 ----------------
__global__ void k_lvl5(const float* __restrict__ Wk) {
    coldot(Wk, g_p2, g_a2v, threadIdx.x);
}

// ---------------- vocab: svt = {emb.v, emb.a1, emb.a2, 0} + fp16 shadow ------
__global__ void k_vocab(const float* __restrict__ emb) {
    __shared__ float4 sV[D4], sA1[D4], sA2[D4];
    for (int i = threadIdx.x; i < D4; i += blockDim.x) {
        sV[i]  = reinterpret_cast<const float4*>(g_v)[i];
        sA1[i] = reinterpret_cast<const float4*>(g_a1v)[i];
        sA2[i] = reinterpret_cast<const float4*>(g_a2v)[i];
    }
    __syncthreads();
    int row = blockIdx.x * 4 + (threadIdx.x >> 5);
    int lane = threadIdx.x & 31;
    if (row >= VV) return;
    const float4* er = reinterpret_cast<const float4*>(emb + (size_t)row * DD);
    float av = 0.f, a1 = 0.f, a2 = 0.f;
#pragma unroll
    for (int i = lane; i < D4; i += 32) {
        float4 e = er[i];
        float4 vv = sV[i], w1 = sA1[i], w2 = sA2[i];
        av += e.x * vv.x + e.y * vv.y + e.z * vv.z + e.w * vv.w;
        a1 += e.x * w1.x + e.y * w1.y + e.z * w1.z + e.w * w1.w;
        a2 += e.x * w2.x + e.y * w2.y + e.z * w2.z + e.w * w2.w;
        __half2 h0 = __floats2half2_rn(e.x, e.y);
        __half2 h1 = __floats2half2_rn(e.z, e.w);
        uint2 u;
        u.x = *reinterpret_cast<unsigned*>(&h0);
        u.y = *reinterpret_cast<unsigned*>(&h1);
        g_embh[(size_t)row * D4 + i] = u;
    }
#pragma unroll
    for (int o = 16; o; o >>= 1) {
        av += __shfl_xor_sync(0xffffffffu, av, o);
        a1 += __shfl_xor_sync(0xffffffffu, a1, o);
        a2 += __shfl_xor_sync(0xffffffffu, a2, o);
    }
    if (lane == 0) g_svt[row] = make_float4(av, a1, a2, 0.f);
}

// ---------------- lens + aspect mean -> x0 -----------------
__global__ void k_lens_aspect(const int* __restrict__ text, const int* __restrict__ asp,
                              const float* __restrict__ emb) {
    int b = blockIdx.x, tid = threadIdx.x;
    __shared__ int s_asp[8];
    __shared__ int s_red[4];
    __shared__ float s_invn;
    if (tid < 8) s_asp[tid] = asp[b * 8 + tid];
    int cnt = 0;
    for (int s = tid; s < SS; s += 128) cnt += (text[b * SS + s] != 0);
#pragma unroll
    for (int o = 16; o; o >>= 1) cnt += __shfl_xor_sync(0xffffffffu, cnt, o);
    if ((tid & 31) == 0) s_red[tid >> 5] = cnt;
    __syncthreads();
    if (tid == 0) {
        g_lens[b] = s_red[0] + s_red[1] + s_red[2] + s_red[3];
        int na = 0;
        for (int a = 0; a < 8; a++) na += (s_asp[a] != 0);
        s_invn = 1.0f / (float)na;
    }
    __syncthreads();
    float invn = s_invn;
    for (int d = tid; d < DD; d += 128) {
        float ssum = 0.f;
#pragma unroll
        for (int a = 0; a < 8; a++) ssum += emb[(size_t)s_asp[a] * DD + d];  // emb[0]==0
        g_x0[b * DD + d] = ssum * invn;
    }
}

// ---------------- MEGA: all 3 hops' softmax + single gather + output --------
__global__ __launch_bounds__(384) void k_mega(const int* __restrict__ text,
                                              float* __restrict__ out) {
    const int NT = 384;
    int b = blockIdx.x, tid = threadIdx.x;
    int lane = tid & 31, wid = tid >> 5;

    __shared__ int   s_idx[SS];
    __shared__ float s_sv[SS], s_t1[SS], s_t2[SS];
    __shared__ float s_c0[SS], s_c1[SS], s_c2[SS];
    __shared__ float s_x0[DD];
    __shared__ float4 s_part[3][4][D4];
    __shared__ float s_am[3][DD];
    __shared__ float s_red[12][3];
    __shared__ float s_b[6];

    // token scalar tables
    for (int s = tid; s < SS; s += NT) {
        int ix = text[b * SS + s];
        s_idx[s] = ix;
        float4 svt = g_svt[ix];
        s_sv[s] = svt.x; s_t1[s] = svt.y; s_t2[s] = svt.z;
    }
    // x0 dots with u2, b1, b2
    float d0 = 0.f, d1 = 0.f, d2 = 0.f;
    if (tid < DD) {
        float xv = g_x0[b * DD + tid];
        s_x0[tid] = xv;
        d0 = xv * g_u2[tid]; d1 = xv * g_b1[tid]; d2 = xv * g_b2[tid];
    }
#pragma unroll
    for (int o = 16; o; o >>= 1) {
        d0 += __shfl_xor_sync(0xffffffffu, d0, o);
        d1 += __shfl_xor_sync(0xffffffffu, d1, o);
        d2 += __shfl_xor_sync(0xffffffffu, d2, o);
    }
    if (lane == 0) { s_red[wid][0] = d0; s_red[wid][1] = d1; s_red[wid][2] = d2; }
    __syncthreads();
    if (tid == 0) {
        float a = 0.f, c = 0.f, e = 0.f;
        for (int w = 0; w < 12; w++) { a += s_red[w][0]; c += s_red[w][1]; e += s_red[w][2]; }
        s_b[0] = a; s_b[1] = c; s_b[2] = e;
    }
    __syncthreads();
    float du2 = s_b[0], db1 = s_b[1], db2 = s_b[2];

    int len = g_lens[b];
    int s0 = SS - len;
    float invlen = 1.0f / (float)len;

    // ---- hop 0 softmax ----
    float ckq0 = g_ck + du2 + g_c2;
    float es = 0.f, S01 = 0.f, S02 = 0.f;
    for (int s = s0 + tid; s < SS; s += NT) {
        float w = 1.0f - (float)(s - s0) * invlen;
        float e = expf(tanhf(w * s_sv[s] + ckq0));
        float ew = e * w;
        s_c0[s] = ew;
        es += e; S01 += ew * s_t1[s]; S02 += ew * s_t2[s];
    }
#pragma unroll
    for (int o = 16; o; o >>= 1) {
        es  += __shfl_xor_sync(0xffffffffu, es, o);
        S01 += __shfl_xor_sync(0xffffffffu, S01, o);
        S02 += __shfl_xor_sync(0xffffffffu, S02, o);
    }
    if (lane == 0) { s_red[wid][0] = es; s_red[wid][1] = S01; s_red[wid][2] = S02; }
    __syncthreads();
    if (tid == 0) {
        float a = 0.f, c = 0.f, e = 0.f;
        for (int w = 0; w < 12; w++) { a += s_red[w][0]; c += s_red[w][1]; e += s_red[w][2]; }
        float inv0 = 1.0f / (a + (float)s0 * expf(tanhf(ckq0)));
        s_b[0] = inv0;
        s_b[1] = inv0 * c;           // am0 . a1
        s_b[2] = inv0 * e;           // am0 . a2
    }
    __syncthreads();
    float inv0 = s_b[0];
    float q1 = s_b[1] + db1 + g_cc1;

    // ---- hop 1 softmax ----
    float ckq1 = g_ck + q1;
    es = 0.f; S01 = 0.f;
    for (int s = s0 + tid; s < SS; s += NT) {
        float w = 1.0f - (float)(s - s0) * invlen;
        float e = expf(tanhf(w * s_sv[s] + ckq1));
        float ew = e * w;
        s_c1[s] = ew;
        es += e; S01 += ew * s_t1[s];
    }
#pragma unroll
    for (int o = 16; o; o >>= 1) {
        es  += __shfl_xor_sync(0xffffffffu, es, o);
        S01 += __shfl_xor_sync(0xffffffffu, S01, o);
    }
    if (lane == 0) { s_red[wid][0] = es; s_red[wid][1] = S01; }
    __syncthreads();
    if (tid == 0) {
        float a = 0.f, c = 0.f;
        for (int w = 0; w < 12; w++) { a += s_red[w][0]; c += s_red[w][1]; }
        float inv1 = 1.0f / (a + (float)s0 * expf(tanhf(ckq1)));
        s_b[3] = inv1;
        s_b[4] = inv1 * c;           // am1 . a1
    }
    __syncthreads();
    float inv1 = s_b[3];
    float q2 = s_b[4] + s_b[2] + db2 + g_cc2;

    // ---- hop 2 softmax ----
    float ckq2 = g_ck + q2;
    es = 0.f;
    for (int s = s0 + tid; s < SS; s += NT) {
        float w = 1.0f - (float)(s - s0) * invlen;
        float e = expf(tanhf(w * s_sv[s] + ckq2));
        s_c2[s] = e * w;
        es += e;
    }
#pragma unroll
    for (int o = 16; o; o >>= 1) es += __shfl_xor_sync(0xffffffffu, es, o);
    if (lane == 0) s_red[wid][0] = es;
    __syncthreads();
    if (tid == 0) {
        float a = 0.f;
        for (int w = 0; w < 12; w++) a += s_red[w][0];
        s_b[5] = 1.0f / (a + (float)s0 * expf(tanhf(ckq2)));
    }
    __syncthreads();
    float inv2 = s_b[5];

    // normalize all coefficient sets
    for (int s = s0 + tid; s < SS; s += NT) {
        s_c0[s] *= inv0; s_c1[s] *= inv1; s_c2[s] *= inv2;
    }
    __syncthreads();

    // ---- single shared gather: am0, am1, am2 ----
    if (tid < 300) {
        int grp = tid / D4;
        int ch = tid - grp * D4;
        float4 a0 = make_float4(0.f, 0.f, 0.f, 0.f);
        float4 a1 = make_float4(0.f, 0.f, 0.f, 0.f);
        float4 a2 = make_float4(0.f, 0.f, 0.f, 0.f);
        int s = s0 + grp;
        for (; s + 28 < SS; s += 32) {
            int ix[8]; float c0[8], c1[8], c2[8];
#pragma unroll
            for (int j = 0; j < 8; j++) {
                int ss = s + 4 * j;
                ix[j] = s_idx[ss]; c0[j] = s_c0[ss]; c1[j] = s_c1[ss]; c2[j] = s_c2[ss];
            }
            uint2 v[8];
#pragma unroll
            for (int j = 0; j < 8; j++) v[j] = g_embh[(size_t)ix[j] * D4 + ch];
#pragma unroll
            for (int j = 0; j < 8; j++) {
                float2 lo = __half22float2(*reinterpret_cast<__half2*>(&v[j].x));
                float2 hi = __half22float2(*reinterpret_cast<__half2*>(&v[j].y));
                a0.x += c0[j] * lo.x; a0.y += c0[j] * lo.y; a0.z += c0[j] * hi.x; a0.w += c0[j] * hi.y;
                a1.x += c1[j] * lo.x; a1.y += c1[j] * lo.y; a1.z += c1[j] * hi.x; a1.w += c1[j] * hi.y;
                a2.x += c2[j] * lo.x; a2.y += c2[j] * lo.y; a2.z += c2[j] * hi.x; a2.w += c2[j] * hi.y;
            }
        }
        for (; s < SS; s += 4) {
            float c0 = s_c0[s], c1 = s_c1[s], c2 = s_c2[s];
            uint2 v = g_embh[(size_t)s_idx[s] * D4 + ch];
            float2 lo = __half22float2(*reinterpret_cast<__half2*>(&v.x));
            float2 hi = __half22float2(*reinterpret_cast<__half2*>(&v.y));
            a0.x += c0 * lo.x; a0.y += c0 * lo.y; a0.z += c0 * hi.x; a0.w += c0 * hi.y;
            a1.x += c1 * lo.x; a1.y += c1 * lo.y; a1.z += c1 * hi.x; a1.w += c1 * hi.y;
            a2.x += c2 * lo.x; a2.y += c2 * lo.y; a2.z += c2 * hi.x; a2.w += c2 * hi.y;
        }
        s_part[0][grp][ch] = a0;
        s_part[1][grp][ch] = a1;
        s_part[2][grp][ch] = a2;
    }
    __syncthreads();
    // reduce 4 groups -> s_am
    if (tid < 225) {
        int a = tid / D4, ch = tid - a * D4;
        float4 g0 = s_part[a][0][ch], g1 = s_part[a][1][ch];
        float4 g2 = s_part[a][2][ch], g3 = s_part[a][3][ch];
        float4 r;
        r.x = (g0.x + g1.x) + (g2.x + g3.x);
        r.y = (g0.y + g1.y) + (g2.y + g3.y);
        r.z = (g0.z + g1.z) + (g2.z + g3.z);
        r.w = (g0.w + g1.w) + (g2.w + g3.w);
        reinterpret_cast<float4*>(s_am[a])[ch] = r;
    }
    __syncthreads();

    // ---- output: out[b] = M2.am2 + M1.am1 + M0.am0 + Mx.x0 + cvec ----
    {
        int p = wid >> 2, src = wid & 3;   // 12 warps exactly
        const float* M = (src == 0) ? (g_M2 + p * DD) : (src == 1) ? (g_M1 + p * DD)
                       : (src == 2) ? (g_M0 + p * DD) : (g_Mx + p * DD);
        const float* vec = (src == 0) ? s_am[2] : (src == 1) ? s_am[1]
                         : (src == 2) ? s_am[0] : s_x0;
        float acc = 0.f;
        for (int d = lane; d < DD; d += 32) acc += M[d] * vec[d];
#pragma unroll
        for (int o = 16; o; o >>= 1) acc += __shfl_xor_sync(0xffffffffu, acc, o);
        if (lane == 0) s_red[wid][0] = acc;
    }
    __syncthreads();
    if (tid < PP) {
        out[b * PP + tid] = g_cvec[tid] + (s_red[tid * 4][0] + s_red[tid * 4 + 1][0])
                                        + (s_red[tid * 4 + 2][0] + s_red[tid * 4 + 3][0]);
    }
}

// ---------------- launch -----------------
extern "C" void kernel_launch(void* const* d_in, const int* in_sizes, int n_in,
                              void* d_out, int out_size) {
    const int*   text = (const int*)d_in[0];
    const int*   asp  = (const int*)d_in[1];
    const float* emb  = (const float*)d_in[2];
    const float* Wx   = (const float*)d_in[3];
    const float* bx   = (const float*)d_in[4];
    const float* Wk   = (const float*)d_in[5];
    const float* bk   = (const float*)d_in[6];
    const float* Wq   = (const float*)d_in[7];
    const float* bq   = (const float*)d_in[8];
    const float* wmlp = (const float*)d_in[9];
    const float* Wp   = (const float*)d_in[10];
    const float* bp   = (const float*)d_in[11];
    const float* Wd   = (const float*)d_in[12];
    const float* bd   = (const float*)d_in[13];
    float* out = (float*)d_out;

    k_lvl1<<<39, 320>>>(Wq, Wk, Wp, Wx, Wd, wmlp, bk, bq, bp, bx);
    k_lvl2<<<11, 320>>>(Wk, Wp, Wx, bx);
    k_lvl3<<<13, 320>>>(Wk, Wp, Wx, Wd, bd);
    k_lvl4<<<7, 320>>>(Wk, Wp, Wx);
    k_lvl5<<<1, 320>>>(Wk);
    k_vocab<<<(VV + 3) / 4, 128>>>(emb);
    k_lens_aspect<<<BB, 128>>>(text, asp, emb);
    k_mega<<<BB, 384>>>(text, out);
}

// round 7
// speedup vs baseline: 3.0690x; 1.3772x over previous
#include <cuda_runtime.h>
#include <cuda_fp16.h>
#include <math.h>

#define BB 512
#define SS 512
#define VV 50000
#define DD 300
#define PP 3
#define D4 75   // DD/4
#define CH 10   // e-chunks per matvec
#define CE 30   // e per chunk

// ---------------- accumulator block (zeroed each launch) ----------------
#define ACCN 11104
__device__ __align__(16) float g_acc[ACCN];
#define pU   (g_acc + 0)
#define pV   (g_acc + 300)
#define pU2  (g_acc + 600)
#define pB1  (g_acc + 900)
#define pB2  (g_acc + 1200)
#define pP1  (g_acc + 1500)
#define pP2  (g_acc + 1800)
#define pA1  (g_acc + 2100)
#define pA2  (g_acc + 2400)
#define pBCV (g_acc + 2700)
#define pG   (g_acc + 3000)
#define pE   (g_acc + 3900)
#define pH   (g_acc + 4800)
#define pF   (g_acc + 5700)
#define pJ   (g_acc + 6600)
#define pM2  (g_acc + 7500)
#define pM1  (g_acc + 8400)
#define pM0  (g_acc + 9300)
#define pMX  (g_acc + 10200)
#define pCV  (g_acc + 11100)

__device__ float g_ck, g_cq, g_c2, g_cc1, g_cc2;
__device__ __align__(16) float4 g_svt[VV];              // {sv, t1, t2, 0}
__device__ __align__(16) uint2 g_embh[(size_t)VV * D4]; // fp16 emb shadow
__device__ float g_x0[BB * DD];
__device__ int   g_lens[BB];

// ---------------- device helpers ----------------
__device__ __forceinline__ float lanedot(const float* __restrict__ a,
                                         const float* __restrict__ b, int lane) {
    float s = 0.f;
    for (int e = lane; e < DD; e += 32) s += a[e] * b[e];
#pragma unroll
    for (int o = 16; o; o >>= 1) s += __shfl_xor_sync(0xffffffffu, s, o);
    return s;
}

// out[f] += sum_{e in chunk} M[e*DD+f] * y[e]   (column access, coalesced in f)
__device__ __forceinline__ void mv_part(const float* __restrict__ M,
                                        const float* __restrict__ y,
                                        float* __restrict__ out, int chunk) {
    __shared__ float sy[CE];
    int t = threadIdx.x;
    if (t < CE) sy[t] = y[chunk * CE + t];
    __syncthreads();
    if (t < DD) {
        float acc = 0.f;
        const float* Mp = M + chunk * CE * DD + t;
#pragma unroll
        for (int e = 0; e < CE; e++) acc += Mp[e * DD] * sy[e];
        atomicAdd(out + t, acc);
    }
}

// out[p][f] += sum_{e in chunk} A[p*DD+e] * B[e*DD+f]  for p=0..2
__device__ __forceinline__ void mm3_part(const float* __restrict__ A,
                                         const float* __restrict__ B,
                                         float* __restrict__ out, int chunk) {
    __shared__ float sa[3][CE];
    int t = threadIdx.x;
    if (t < 3 * CE) sa[t / CE][t % CE] = A[(t / CE) * DD + chunk * CE + (t % CE)];
    __syncthreads();
    if (t < DD) {
        float a0 = 0.f, a1 = 0.f, a2 = 0.f;
        const float* Bp = B + chunk * CE * DD + t;
#pragma unroll
        for (int e = 0; e < CE; e++) {
            float b = Bp[e * DD];
            a0 += sa[0][e] * b; a1 += sa[1][e] * b; a2 += sa[2][e] * b;
        }
        atomicAdd(out + t, a0);
        atomicAdd(out + DD + t, a1);
        atomicAdd(out + 2 * DD + t, a2);
    }
}

// ---------------- init: zero accumulators ----------------
__global__ void k_init() {
    int i = blockIdx.x * blockDim.x + threadIdx.x;
    if (i < ACCN / 4) reinterpret_cast<float4*>(g_acc)[i] = make_float4(0.f, 0.f, 0.f, 0.f);
}

// ---------------- level 1 ----------------
// u += Wq^T wq ; v += Wk^T wk ; G += Wd@Wp ; E += Wd@Wx ; bcv = Wp@bk + bp + bx ; ck, cq
__global__ void k_lvl1(const float* __restrict__ Wq, const float* __restrict__ Wk,
                       const float* __restrict__ Wp, const float* __restrict__ Wx,
                       const float* __restrict__ Wd, const float* __restrict__ wmlp,
                       const float* __restrict__ bk, const float* __restrict__ bq,
                       const float* __restrict__ bp, const float* __restrict__ bx) {
    int b = blockIdx.x, t = threadIdx.x;
    int lane = t & 31, wid = t >> 5;
    if (b < 10) {
        mv_part(Wq, wmlp + DD, pU, b);
    } else if (b < 20) {
        mv_part(Wk, wmlp, pV, b - 10);
    } else if (b < 30) {
        mm3_part(Wd, Wp, pG, b - 20);
    } else if (b < 40) {
        mm3_part(Wd, Wx, pE, b - 30);
    } else if (b < 70) {
        int row = (b - 40) * 10 + wid;   // 30 blocks x 10 warps = 300 rows
        if (row < DD) {
            float s = lanedot(Wp + row * DD, bk, lane);
            if (lane == 0) pBCV[row] = s + bp[row] + bx[row];
        }
    } else {
        if (wid == 0) { float s = lanedot(bk, wmlp, lane); if (lane == 0) g_ck = s; }
        if (wid == 1) { float s = lanedot(bq, wmlp + DD, lane); if (lane == 0) g_cq = s; }
    }
}

// ---------------- level 2 ----------------
// u2 += Wx^T u ; M2 += G@Wk ; H += E@Wp ; F += E@Wx ; c2 = bx.u + cq
__global__ void k_lvl2(const float* __restrict__ Wk, const float* __restrict__ Wp,
                       const float* __restrict__ Wx, const float* __restrict__ bx) {
    int b = blockIdx.x, t = threadIdx.x;
    int lane = t & 31, wid = t >> 5;
    if (b < 10) {
        mv_part(Wx, pU, pU2, b);
    } else if (b < 20) {
        mm3_part(pG, Wk, pM2, b - 10);
    } else if (b < 30) {
        mm3_part(pE, Wp, pH, b - 20);
    } else if (b < 40) {
        mm3_part(pE, Wx, pF, b - 30);
    } else {
        if (wid == 0) { float s = lanedot(bx, pU, lane); if (lane == 0) g_c2 = s + g_cq; }
    }
}

// ---------------- level 3 ----------------
// b1 += Wx^T u2 ; p1 += Wp^T u2 ; M1 += H@Wk ; Mx += F@Wx ; J += F@Wp ;
// cc1 = bcv.u2 + c2 ; cvec = bd + (Wd+E+F)@bcv
__global__ void k_lvl3(const float* __restrict__ Wk, const float* __restrict__ Wp,
                       const float* __restrict__ Wx, const float* __restrict__ Wd,
                       const float* __restrict__ bd) {
    int b = blockIdx.x, t = threadIdx.x;
    int lane = t & 31, wid = t >> 5;
    if (b < 10) {
        mv_part(Wx, pU2, pB1, b);
    } else if (b < 20) {
        mv_part(Wp, pU2, pP1, b - 10);
    } else if (b < 30) {
        mm3_part(pH, Wk, pM1, b - 20);
    } else if (b < 40) {
        mm3_part(pF, Wx, pMX, b - 30);
    } else if (b < 50) {
        mm3_part(pF, Wp, pJ, b - 40);
    } else {
        if (wid == 0) { float s = lanedot(pBCV, pU2, lane); if (lane == 0) g_cc1 = s + g_c2; }
        if (wid >= 1 && wid <= 3) {
            int p = wid - 1;
            float s = 0.f;
            for (int e = lane; e < DD; e += 32)
                s += (Wd[p * DD + e] + pE[p * DD + e] + pF[p * DD + e]) * pBCV[e];
#pragma unroll
            for (int o = 16; o; o >>= 1) s += __shfl_xor_sync(0xffffffffu, s, o);
            if (lane == 0) pCV[p] = s + bd[p];
        }
    }
}

// ---------------- level 4 ----------------
// a1 += Wk^T p1 ; b2 += Wx^T b1 ; p2 += Wp^T b1 ; M0 += J@Wk ; cc2 = bcv.b1 + cc1
__global__ void k_lvl4(const float* __restrict__ Wk, const float* __restrict__ Wp,
                       const float* __restrict__ Wx) {
    int b = blockIdx.x, t = threadIdx.x;
    int lane = t & 31, wid = t >> 5;
    if (b < 10) {
        mv_part(Wk, pP1, pA1, b);
    } else if (b < 20) {
        mv_part(Wx, pB1, pB2, b - 10);
    } else if (b < 30) {
        mv_part(Wp, pB1, pP2, b - 20);
    } else if (b < 40) {
        mm3_part(pJ, Wk, pM0, b - 30);
    } else {
        if (wid == 0) { float s = lanedot(pBCV, pB1, lane); if (lane == 0) g_cc2 = s + g_cc1; }
    }
}

// ---------------- level 5: a2 += Wk^T p2 ----------------
__global__ void k_lvl5(const float* __restrict__ Wk) {
    mv_part(Wk, pP2, pA2, blockIdx.x);
}

// ---------------- vocab: svt = {emb.v, emb.a1, emb.a2, 0} + fp16 shadow ------
__global__ void k_vocab(const float* __restrict__ emb) {
    __shared__ float4 sV[D4], sA1[D4], sA2[D4];
    for (int i = threadIdx.x; i < D4; i += blockDim.x) {
        sV[i]  = reinterpret_cast<const float4*>(pV)[i];
        sA1[i] = reinterpret_cast<const float4*>(pA1)[i];
        sA2[i] = reinterpret_cast<const float4*>(pA2)[i];
    }
    __syncthreads();
    int row = blockIdx.x * 4 + (threadIdx.x >> 5);
    int lane = threadIdx.x & 31;
    if (row >= VV) return;
    const float4* er = reinterpret_cast<const float4*>(emb + (size_t)row * DD);
    float av = 0.f, a1 = 0.f, a2 = 0.f;
#pragma unroll
    for (int i = lane; i < D4; i += 32) {
        float4 e = er[i];
        float4 vv = sV[i], w1 = sA1[i], w2 = sA2[i];
        av += e.x * vv.x + e.y * vv.y + e.z * vv.z + e.w * vv.w;
        a1 += e.x * w1.x + e.y * w1.y + e.z * w1.z + e.w * w1.w;
        a2 += e.x * w2.x + e.y * w2.y + e.z * w2.z + e.w * w2.w;
        __half2 h0 = __floats2half2_rn(e.x, e.y);
        __half2 h1 = __floats2half2_rn(e.z, e.w);
        uint2 u;
        u.x = *reinterpret_cast<unsigned*>(&h0);
        u.y = *reinterpret_cast<unsigned*>(&h1);
        g_embh[(size_t)row * D4 + i] = u;
    }
#pragma unroll
    for (int o = 16; o; o >>= 1) {
        av += __shfl_xor_sync(0xffffffffu, av, o);
        a1 += __shfl_xor_sync(0xffffffffu, a1, o);
        a2 += __shfl_xor_sync(0xffffffffu, a2, o);
    }
    if (lane == 0) g_svt[row] = make_float4(av, a1, a2, 0.f);
}

// ---------------- lens + aspect mean -> x0 -----------------
__global__ void k_lens_aspect(const int* __restrict__ text, const int* __restrict__ asp,
                              const float* __restrict__ emb) {
    int b = blockIdx.x, tid = threadIdx.x;
    __shared__ int s_asp[8];
    __shared__ int s_red[4];
    __shared__ float s_invn;
    if (tid < 8) s_asp[tid] = asp[b * 8 + tid];
    int cnt = 0;
    for (int s = tid; s < SS; s += 128) cnt += (text[b * SS + s] != 0);
#pragma unroll
    for (int o = 16; o; o >>= 1) cnt += __shfl_xor_sync(0xffffffffu, cnt, o);
    if ((tid & 31) == 0) s_red[tid >> 5] = cnt;
    __syncthreads();
    if (tid == 0) {
        g_lens[b] = s_red[0] + s_red[1] + s_red[2] + s_red[3];
        int na = 0;
        for (int a = 0; a < 8; a++) na += (s_asp[a] != 0);
        s_invn = 1.0f / (float)na;
    }
    __syncthreads();
    float invn = s_invn;
    for (int d = tid; d < DD; d += 128) {
        float ssum = 0.f;
#pragma unroll
        for (int a = 0; a < 8; a++) ssum += emb[(size_t)s_asp[a] * DD + d];  // emb[0]==0
        g_x0[b * DD + d] = ssum * invn;
    }
}

// ---------------- MEGA: all 3 hops' softmax + single gather + output --------
__global__ __launch_bounds__(384) void k_mega(const int* __restrict__ text,
                                              float* __restrict__ out) {
    const int NT = 384;
    int b = blockIdx.x, tid = threadIdx.x;
    int lane = tid & 31, wid = tid >> 5;

    __shared__ int   s_idx[SS];
    __shared__ float s_sv[SS], s_t1[SS], s_t2[SS];
    __shared__ float s_c0[SS], s_c1[SS], s_c2[SS];
    __shared__ float s_x0[DD];
    __shared__ float4 s_part[3][4][D4];
    __shared__ float s_am[3][DD];
    __shared__ float s_red[12][3];
    __shared__ float s_b[6];

    for (int s = tid; s < SS; s += NT) {
        int ix = text[b * SS + s];
        s_idx[s] = ix;
        float4 svt = g_svt[ix];
        s_sv[s] = svt.x; s_t1[s] = svt.y; s_t2[s] = svt.z;
    }
    float d0 = 0.f, d1 = 0.f, d2 = 0.f;
    if (tid < DD) {
        float xv = g_x0[b * DD + tid];
        s_x0[tid] = xv;
        d0 = xv * pU2[tid]; d1 = xv * pB1[tid]; d2 = xv * pB2[tid];
    }
#pragma unroll
    for (int o = 16; o; o >>= 1) {
        d0 += __shfl_xor_sync(0xffffffffu, d0, o);
        d1 += __shfl_xor_sync(0xffffffffu, d1, o);
        d2 += __shfl_xor_sync(0xffffffffu, d2, o);
    }
    if (lane == 0) { s_red[wid][0] = d0; s_red[wid][1] = d1; s_red[wid][2] = d2; }
    __syncthreads();
    if (tid == 0) {
        float a = 0.f, c = 0.f, e = 0.f;
        for (int w = 0; w < 12; w++) { a += s_red[w][0]; c += s_red[w][1]; e += s_red[w][2]; }
        s_b[0] = a; s_b[1] = c; s_b[2] = e;
    }
    __syncthreads();
    float du2 = s_b[0], db1 = s_b[1], db2 = s_b[2];

    int len = g_lens[b];
    int s0 = SS - len;
    float invlen = 1.0f / (float)len;

    // hop 0
    float ckq0 = g_ck + du2 + g_c2;
    float es = 0.f, S01 = 0.f, S02 = 0.f;
    for (int s = s0 + tid; s < SS; s += NT) {
        float w = 1.0f - (float)(s - s0) * invlen;
        float e = expf(tanhf(w * s_sv[s] + ckq0));
        float ew = e * w;
        s_c0[s] = ew;
        es += e; S01 += ew * s_t1[s]; S02 += ew * s_t2[s];
    }
#pragma unroll
    for (int o = 16; o; o >>= 1) {
        es  += __shfl_xor_sync(0xffffffffu, es, o);
        S01 += __shfl_xor_sync(0xffffffffu, S01, o);
        S02 += __shfl_xor_sync(0xffffffffu, S02, o);
    }
    if (lane == 0) { s_red[wid][0] = es; s_red[wid][1] = S01; s_red[wid][2] = S02; }
    __syncthreads();
    if (tid == 0) {
        float a = 0.f, c = 0.f, e = 0.f;
        for (int w = 0; w < 12; w++) { a += s_red[w][0]; c += s_red[w][1]; e += s_red[w][2]; }
        float inv0 = 1.0f / (a + (float)s0 * expf(tanhf(ckq0)));
        s_b[0] = inv0;
        s_b[1] = inv0 * c;
        s_b[2] = inv0 * e;
    }
    __syncthreads();
    float inv0 = s_b[0];
    float q1 = s_b[1] + db1 + g_cc1;

    // hop 1
    float ckq1 = g_ck + q1;
    es = 0.f; S01 = 0.f;
    for (int s = s0 + tid; s < SS; s += NT) {
        float w = 1.0f - (float)(s - s0) * invlen;
        float e = expf(tanhf(w * s_sv[s] + ckq1));
        float ew = e * w;
        s_c1[s] = ew;
        es += e; S01 += ew * s_t1[s];
    }
#pragma unroll
    for (int o = 16; o; o >>= 1) {
        es  += __shfl_xor_sync(0xffffffffu, es, o);
        S01 += __shfl_xor_sync(0xffffffffu, S01, o);
    }
    if (lane == 0) { s_red[wid][0] = es; s_red[wid][1] = S01; }
    __syncthreads();
    if (tid == 0) {
        float a = 0.f, c = 0.f;
        for (int w = 0; w < 12; w++) { a += s_red[w][0]; c += s_red[w][1]; }
        float inv1 = 1.0f / (a + (float)s0 * expf(tanhf(ckq1)));
        s_b[3] = inv1;
        s_b[4] = inv1 * c;
    }
    __syncthreads();
    float inv1 = s_b[3];
    float q2 = s_b[4] + s_b[2] + db2 + g_cc2;

    // hop 2
    float ckq2 = g_ck + q2;
    es = 0.f;
    for (int s = s0 + tid; s < SS; s += NT) {
        float w = 1.0f - (float)(s - s0) * invlen;
        float e = expf(tanhf(w * s_sv[s] + ckq2));
        s_c2[s] = e * w;
        es += e;
    }
#pragma unroll
    for (int o = 16; o; o >>= 1) es += __shfl_xor_sync(0xffffffffu, es, o);
    if (lane == 0) s_red[wid][0] = es;
    __syncthreads();
    if (tid == 0) {
        float a = 0.f;
        for (int w = 0; w < 12; w++) a += s_red[w][0];
        s_b[5] = 1.0f / (a + (float)s0 * expf(tanhf(ckq2)));
    }
    __syncthreads();
    float inv2 = s_b[5];

    for (int s = s0 + tid; s < SS; s += NT) {
        s_c0[s] *= inv0; s_c1[s] *= inv1; s_c2[s] *= inv2;
    }
    __syncthreads();

    // single shared gather: am0, am1, am2
    if (tid < 300) {
        int grp = tid / D4;
        int ch = tid - grp * D4;
        float4 a0 = make_float4(0.f, 0.f, 0.f, 0.f);
        float4 a1 = make_float4(0.f, 0.f, 0.f, 0.f);
        float4 a2 = make_float4(0.f, 0.f, 0.f, 0.f);
        int s = s0 + grp;
        for (; s + 28 < SS; s += 32) {
            int ix[8]; float c0[8], c1[8], c2[8];
#pragma unroll
            for (int j = 0; j < 8; j++) {
                int ss = s + 4 * j;
                ix[j] = s_idx[ss]; c0[j] = s_c0[ss]; c1[j] = s_c1[ss]; c2[j] = s_c2[ss];
            }
            uint2 v[8];
#pragma unroll
            for (int j = 0; j < 8; j++) v[j] = g_embh[(size_t)ix[j] * D4 + ch];
#pragma unroll
            for (int j = 0; j < 8; j++) {
                float2 lo = __half22float2(*reinterpret_cast<__half2*>(&v[j].x));
                float2 hi = __half22float2(*reinterpret_cast<__half2*>(&v[j].y));
                a0.x += c0[j] * lo.x; a0.y += c0[j] * lo.y; a0.z += c0[j] * hi.x; a0.w += c0[j] * hi.y;
                a1.x += c1[j] * lo.x; a1.y += c1[j] * lo.y; a1.z += c1[j] * hi.x; a1.w += c1[j] * hi.y;
                a2.x += c2[j] * lo.x; a2.y += c2[j] * lo.y; a2.z += c2[j] * hi.x; a2.w += c2[j] * hi.y;
            }
        }
        for (; s < SS; s += 4) {
            float c0 = s_c0[s], c1 = s_c1[s], c2 = s_c2[s];
            uint2 v = g_embh[(size_t)s_idx[s] * D4 + ch];
            float2 lo = __half22float2(*reinterpret_cast<__half2*>(&v.x));
            float2 hi = __half22float2(*reinterpret_cast<__half2*>(&v.y));
            a0.x += c0 * lo.x; a0.y += c0 * lo.y; a0.z += c0 * hi.x; a0.w += c0 * hi.y;
            a1.x += c1 * lo.x; a1.y += c1 * lo.y; a1.z += c1 * hi.x; a1.w += c1 * hi.y;
            a2.x += c2 * lo.x; a2.y += c2 * lo.y; a2.z += c2 * hi.x; a2.w += c2 * hi.y;
        }
        s_part[0][grp][ch] = a0;
        s_part[1][grp][ch] = a1;
        s_part[2][grp][ch] = a2;
    }
    __syncthreads();
    if (tid < 225) {
        int a = tid / D4, ch = tid - a * D4;
        float4 g0 = s_part[a][0][ch], g1 = s_part[a][1][ch];
        float4 g2 = s_part[a][2][ch], g3 = s_part[a][3][ch];
        float4 r;
        r.x = (g0.x + g1.x) + (g2.x + g3.x);
        r.y = (g0.y + g1.y) + (g2.y + g3.y);
        r.z = (g0.z + g1.z) + (g2.z + g3.z);
        r.w = (g0.w + g1.w) + (g2.w + g3.w);
        reinterpret_cast<float4*>(s_am[a])[ch] = r;
    }
    __syncthreads();

    // output: out[b] = M2.am2 + M1.am1 + M0.am0 + Mx.x0 + cvec
    {
        int p = wid >> 2, src = wid & 3;
        const float* M = (src == 0) ? (pM2 + p * DD) : (src == 1) ? (pM1 + p * DD)
                       : (src == 2) ? (pM0 + p * DD) : (pMX + p * DD);
        const float* vec = (src == 0) ? s_am[2] : (src == 1) ? s_am[1]
                         : (src == 2) ? s_am[0] : s_x0;
        float acc = 0.f;
        for (int d = lane; d < DD; d += 32) acc += M[d] * vec[d];
#pragma unroll
        for (int o = 16; o; o >>= 1) acc += __shfl_xor_sync(0xffffffffu, acc, o);
        if (lane == 0) s_red[wid][0] = acc;
    }
    __syncthreads();
    if (tid < PP) {
        out[b * PP + tid] = pCV[tid] + (s_red[tid * 4][0] + s_red[tid * 4 + 1][0])
                                     + (s_red[tid * 4 + 2][0] + s_red[tid * 4 + 3][0]);
    }
}

// ---------------- launch -----------------
extern "C" void kernel_launch(void* const* d_in, const int* in_sizes, int n_in,
                              void* d_out, int out_size) {
    const int*   text = (const int*)d_in[0];
    const int*   asp  = (const int*)d_in[1];
    const float* emb  = (const float*)d_in[2];
    const float* Wx   = (const float*)d_in[3];
    const float* bx   = (const float*)d_in[4];
    const float* Wk   = (const float*)d_in[5];
    const float* bk   = (const float*)d_in[6];
    const float* Wq   = (const float*)d_in[7];
    const float* bq   = (const float*)d_in[8];
    const float* wmlp = (const float*)d_in[9];
    const float* Wp   = (const float*)d_in[10];
    const float* bp   = (const float*)d_in[11];
    const float* Wd   = (const float*)d_in[12];
    const float* bd   = (const float*)d_in[13];
    float* out = (float*)d_out;

    k_init<<<11, 256>>>();
    k_lvl1<<<71, 320>>>(Wq, Wk, Wp, Wx, Wd, wmlp, bk, bq, bp, bx);
    k_lvl2<<<41, 320>>>(Wk, Wp, Wx, bx);
    k_lvl3<<<51, 320>>>(Wk, Wp, Wx, Wd, bd);
    k_lvl4<<<41, 320>>>(Wk, Wp, Wx);
    k_lvl5<<<10, 320>>>(Wk);
    k_vocab<<<(VV + 3) / 4, 128>>>(emb);
    k_lens_aspect<<<BB, 128>>>(text, asp, emb);
    k_mega<<<BB, 384>>>(text, out);
}

// round 9
// speedup vs baseline: 3.2310x; 1.0528x over previous
#include <cuda_runtime.h>
#include <cuda_fp16.h>
#include <math.h>

#define BB 512
#define SS 512
#define VV 50000
#define DD 300
#define PP 3
#define D4 75   // DD/4
#define CE 30   // e per chunk
#define NCHAIN 120

// ---------------- accumulator block (zeroed in-kernel) ----------------
#define ACCN 11104
__device__ __align__(16) float g_acc[ACCN];
#define pU   (g_acc + 0)
#define pV   (g_acc + 300)
#define pU2  (g_acc + 600)
#define pB1  (g_acc + 900)
#define pB2  (g_acc + 1200)
#define pP1  (g_acc + 1500)
#define pP2  (g_acc + 1800)
#define pA1  (g_acc + 2100)
#define pA2  (g_acc + 2400)
#define pBCV (g_acc + 2700)
#define pG   (g_acc + 3000)
#define pE   (g_acc + 3900)
#define pH   (g_acc + 4800)
#define pF   (g_acc + 5700)
#define pJ   (g_acc + 6600)
#define pM2  (g_acc + 7500)
#define pM1  (g_acc + 8400)
#define pM0  (g_acc + 9300)
#define pMX  (g_acc + 10200)
#define pCV  (g_acc + 11100)

__device__ float g_ck, g_cq, g_c2, g_cc1, g_cc2;
__device__ __align__(16) float4 g_svt[VV];              // {sv, t1, t2, 0}
__device__ __align__(16) uint2 g_embh[(size_t)VV * D4]; // fp16 emb shadow

// ---------------- replay-safe grid barrier ----------------
__device__ volatile unsigned g_barphase[8];
__device__ unsigned g_barcnt[8];

__device__ __forceinline__ void gridbar(int slot) {
    __syncthreads();
    if (threadIdx.x == 0) {
        __threadfence();
        unsigned ph = g_barphase[slot];
        unsigned t = atomicAdd(&g_barcnt[slot], 1u);
        if (t == NCHAIN - 1) {
            g_barcnt[slot] = 0;            // reset for next replay
            __threadfence();
            atomicAdd((unsigned*)&g_barphase[slot], 1u);
        } else {
            while (g_barphase[slot] == ph) { __nanosleep(64); }
        }
        __threadfence();
    }
    __syncthreads();
}

// ---------------- device helpers ----------------
__device__ __forceinline__ float lanedot(const float* __restrict__ a,
                                         const float* __restrict__ b, int lane) {
    float s = 0.f;
    for (int e = lane; e < DD; e += 32) s += a[e] * b[e];
#pragma unroll
    for (int o = 16; o; o >>= 1) s += __shfl_xor_sync(0xffffffffu, s, o);
    return s;
}

// out[f] += sum_{e in chunk} M[e*DD+f] * y[e]
__device__ __forceinline__ void mv_part(const float* __restrict__ M,
                                        const float* __restrict__ y,
                                        float* __restrict__ out, int chunk) {
    __shared__ float sy[CE];
    int t = threadIdx.x;
    if (t < CE) sy[t] = y[chunk * CE + t];
    __syncthreads();
    if (t < DD) {
        float acc = 0.f;
        const float* Mp = M + chunk * CE * DD + t;
#pragma unroll
        for (int e = 0; e < CE; e++) acc += Mp[e * DD] * sy[e];
        atomicAdd(out + t, acc);
    }
    __syncthreads();
}

// out[p][f] += sum_{e in chunk} A[p*DD+e] * B[e*DD+f]  for p=0..2
__device__ __forceinline__ void mm3_part(const float* __restrict__ A,
                                         const float* __restrict__ B,
                                         float* __restrict__ out, int chunk) {
    __shared__ float sa[3][CE];
    int t = threadIdx.x;
    if (t < 3 * CE) sa[t / CE][t % CE] = A[(t / CE) * DD + chunk * CE + (t % CE)];
    __syncthreads();
    if (t < DD) {
        float a0 = 0.f, a1 = 0.f, a2 = 0.f;
        const float* Bp = B + chunk * CE * DD + t;
#pragma unroll
        for (int e = 0; e < CE; e++) {
            float b = Bp[e * DD];
            a0 += sa[0][e] * b; a1 += sa[1][e] * b; a2 += sa[2][e] * b;
        }
        atomicAdd(out + t, a0);
        atomicAdd(out + DD + t, a1);
        atomicAdd(out + 2 * DD + t, a2);
    }
    __syncthreads();
}

// ---------------- fused prep chain: zero + 5 levels, one launch ----------
__global__ __launch_bounds__(320) void k_prep(
        const float* __restrict__ Wq, const float* __restrict__ Wk,
        const float* __restrict__ Wp, const float* __restrict__ Wx,
        const float* __restrict__ Wd, const float* __restrict__ wmlp,
        const float* __restrict__ bk, const float* __restrict__ bq,
        const float* __restrict__ bp, const float* __restrict__ bx,
        const float* __restrict__ bd) {
    int b = blockIdx.x, t = threadIdx.x;
    int lane = t & 31, wid = t >> 5;

    // level 0: zero accumulators
    for (int i = b * 320 + t; i < ACCN; i += NCHAIN * 320) g_acc[i] = 0.f;
    gridbar(0);

    // level 1: u, v, G, E, bcv, ck/cq
    if (b < 10) {
        mv_part(Wq, wmlp + DD, pU, b);
    } else if (b < 20) {
        mv_part(Wk, wmlp, pV, b - 10);
    } else if (b < 30) {
        mm3_part(Wd, Wp, pG, b - 20);
    } else if (b < 40) {
        mm3_part(Wd, Wx, pE, b - 30);
    } else if (b < 70) {
        int row = (b - 40) * 10 + wid;
        if (row < DD) {
            float s = lanedot(Wp + row * DD, bk, lane);
            if (lane == 0) pBCV[row] = s + bp[row] + bx[row];
        }
    } else if (b == 70) {
        if (wid == 0) { float s = lanedot(bk, wmlp, lane); if (lane == 0) g_ck = s; }
        if (wid == 1) { float s = lanedot(bq, wmlp + DD, lane); if (lane == 0) g_cq = s; }
    }
    gridbar(1);

    // level 2: u2, M2, H, F, c2
    if (b < 10) {
        mv_part(Wx, pU, pU2, b);
    } else if (b < 20) {
        mm3_part(pG, Wk, pM2, b - 10);
    } else if (b < 30) {
        mm3_part(pE, Wp, pH, b - 20);
    } else if (b < 40) {
        mm3_part(pE, Wx, pF, b - 30);
    } else if (b == 40) {
        if (wid == 0) { float s = lanedot(bx, pU, lane); if (lane == 0) g_c2 = s + g_cq; }
    }
    gridbar(2);

    // level 3: b1, p1, M1, Mx, J, cc1, cvec
    if (b < 10) {
        mv_part(Wx, pU2, pB1, b);
    } else if (b < 20) {
        mv_part(Wp, pU2, pP1, b - 10);
    } else if (b < 30) {
        mm3_part(pH, Wk, pM1, b - 20);
    } else if (b < 40) {
        mm3_part(pF, Wx, pMX, b - 30);
    } else if (b < 50) {
        mm3_part(pF, Wp, pJ, b - 40);
    } else if (b == 50) {
        if (wid == 0) { float s = lanedot(pBCV, pU2, lane); if (lane == 0) g_cc1 = s + g_c2; }
        if (wid >= 1 && wid <= 3) {
            int p = wid - 1;
            float s = 0.f;
            for (int e = lane; e < DD; e += 32)
                s += (Wd[p * DD + e] + pE[p * DD + e] + pF[p * DD + e]) * pBCV[e];
#pragma unroll
            for (int o = 16; o; o >>= 1) s += __shfl_xor_sync(0xffffffffu, s, o);
            if (lane == 0) pCV[p] = s + bd[p];
        }
    }
    gridbar(3);

    // level 4: a1, b2, p2, M0, cc2
    if (b < 10) {
        mv_part(Wk, pP1, pA1, b);
    } else if (b < 20) {
        mv_part(Wx, pB1, pB2, b - 10);
    } else if (b < 30) {
        mv_part(Wp, pB1, pP2, b - 20);
    } else if (b < 40) {
        mm3_part(pJ, Wk, pM0, b - 30);
    } else if (b == 40) {
        if (wid == 0) { float s = lanedot(pBCV, pB1, lane); if (lane == 0) g_cc2 = s + g_cc1; }
    }
    gridbar(4);

    // level 5: a2
    if (b < 10) mv_part(Wk, pP2, pA2, b);
}

// ---------------- vocab: svt = {emb.v, emb.a1, emb.a2, 0} + fp16 shadow ------
__global__ void k_vocab(const float* __restrict__ emb) {
    __shared__ __align__(16) float4 sV[D4], sA1[D4], sA2[D4];
    for (int i = threadIdx.x; i < D4; i += blockDim.x) {
        sV[i]  = reinterpret_cast<const float4*>(pV)[i];
        sA1[i] = reinterpret_cast<const float4*>(pA1)[i];
        sA2[i] = reinterpret_cast<const float4*>(pA2)[i];
    }
    __syncthreads();
    int row = blockIdx.x * 4 + (threadIdx.x >> 5);
    int lane = threadIdx.x & 31;
    if (row >= VV) return;
    const float4* er = reinterpret_cast<const float4*>(emb + (size_t)row * DD);
    float av = 0.f, a1 = 0.f, a2 = 0.f;
#pragma unroll
    for (int i = lane; i < D4; i += 32) {
        float4 e = er[i];
        float4 vv = sV[i], w1 = sA1[i], w2 = sA2[i];
        av += e.x * vv.x + e.y * vv.y + e.z * vv.z + e.w * vv.w;
        a1 += e.x * w1.x + e.y * w1.y + e.z * w1.z + e.w * w1.w;
        a2 += e.x * w2.x + e.y * w2.y + e.z * w2.z + e.w * w2.w;
        __half2 h0 = __floats2half2_rn(e.x, e.y);
        __half2 h1 = __floats2half2_rn(e.z, e.w);
        uint2 u;
        u.x = *reinterpret_cast<unsigned*>(&h0);
        u.y = *reinterpret_cast<unsigned*>(&h1);
        g_embh[(size_t)row * D4 + i] = u;
    }
#pragma unroll
    for (int o = 16; o; o >>= 1) {
        av += __shfl_xor_sync(0xffffffffu, av, o);
        a1 += __shfl_xor_sync(0xffffffffu, a1, o);
        a2 += __shfl_xor_sync(0xffffffffu, a2, o);
    }
    if (lane == 0) g_svt[row] = make_float4(av, a1, a2, 0.f);
}

// ---------------- MEGA: lens + x0 + 3 softmaxes + single gather + output ----
__global__ __launch_bounds__(384) void k_mega(const int* __restrict__ text,
                                              const int* __restrict__ asp,
                                              float* __restrict__ out) {
    const int NT = 384;
    int b = blockIdx.x, tid = threadIdx.x;
    int lane = tid & 31, wid = tid >> 5;

    __shared__ int   s_idx[SS];
    __shared__ int   s_asp[8];
    __shared__ int   s_len;
    __shared__ float s_sv[SS], s_t1[SS], s_t2[SS];
    __shared__ float s_c0[SS], s_c1[SS], s_c2[SS];
    __shared__ __align__(16) float s_x0[DD];
    __shared__ __align__(16) float4 s_part[3][4][D4];
    __shared__ __align__(16) float s_am[3][DD];
    __shared__ float s_red[12][3];
    __shared__ float s_b[6];

    if (tid < 8) s_asp[tid] = asp[b * 8 + tid];
    int cnt = 0;
    for (int s = tid; s < SS; s += NT) {
        int ix = text[b * SS + s];
        s_idx[s] = ix;
        cnt += (ix != 0);
        float4 svt = g_svt[ix];
        s_sv[s] = svt.x; s_t1[s] = svt.y; s_t2[s] = svt.z;
    }
#pragma unroll
    for (int o = 16; o; o >>= 1) cnt += __shfl_xor_sync(0xffffffffu, cnt, o);
    if (lane == 0) s_red[wid][0] = (float)cnt;
    __syncthreads();
    if (tid == 0) {
        float a = 0.f;
        for (int w = 0; w < 12; w++) a += s_red[w][0];
        s_len = (int)a;
    }
    // x0 from fp16 shadow: 75 threads, one float4 chunk each over 8 aspect rows
    if (tid < D4) {
        int na = 0;
#pragma unroll
        for (int j = 0; j < 8; j++) na += (s_asp[j] != 0);
        float invn = 1.0f / (float)na;
        float4 acc = make_float4(0.f, 0.f, 0.f, 0.f);
#pragma unroll
        for (int j = 0; j < 8; j++) {
            uint2 v = g_embh[(size_t)s_asp[j] * D4 + tid];   // row 0 is zeros
            float2 lo = __half22float2(*reinterpret_cast<__half2*>(&v.x));
            float2 hi = __half22float2(*reinterpret_cast<__half2*>(&v.y));
            acc.x += lo.x; acc.y += lo.y; acc.z += hi.x; acc.w += hi.y;
        }
        acc.x *= invn; acc.y *= invn; acc.z *= invn; acc.w *= invn;
        reinterpret_cast<float4*>(s_x0)[tid] = acc;
    }
    __syncthreads();

    float d0 = 0.f, d1 = 0.f, d2 = 0.f;
    if (tid < DD) {
        float xv = s_x0[tid];
        d0 = xv * pU2[tid]; d1 = xv * pB1[tid]; d2 = xv * pB2[tid];
    }
#pragma unroll
    for (int o = 16; o; o >>= 1) {
        d0 += __shfl_xor_sync(0xffffffffu, d0, o);
        d1 += __shfl_xor_sync(0xffffffffu, d1, o);
        d2 += __shfl_xor_sync(0xffffffffu, d2, o);
    }
    if (lane == 0) { s_red[wid][0] = d0; s_red[wid][1] = d1; s_red[wid][2] = d2; }
    __syncthreads();
    if (tid == 0) {
        float a = 0.f, c = 0.f, e = 0.f;
        for (int w = 0; w < 12; w++) { a += s_red[w][0]; c += s_red[w][1]; e += s_red[w][2]; }
        s_b[0] = a; s_b[1] = c; s_b[2] = e;
    }
    __syncthreads();
    float du2 = s_b[0], db1 = s_b[1], db2 = s_b[2];

    int len = s_len;
    int s0 = SS - len;
    float invlen = 1.0f / (float)len;

    // hop 0
    float ckq0 = g_ck + du2 + g_c2;
    float es = 0.f, S01 = 0.f, S02 = 0.f;
    for (int s = s0 + tid; s < SS; s += NT) {
        float w = 1.0f - (float)(s - s0) * invlen;
        float e = expf(tanhf(w * s_sv[s] + ckq0));
        float ew = e * w;
        s_c0[s] = ew;
        es += e; S01 += ew * s_t1[s]; S02 += ew * s_t2[s];
    }
#pragma unroll
    for (int o = 16; o; o >>= 1) {
        es  += __shfl_xor_sync(0xffffffffu, es, o);
        S01 += __shfl_xor_sync(0xffffffffu, S01, o);
        S02 += __shfl_xor_sync(0xffffffffu, S02, o);
    }
    if (lane == 0) { s_red[wid][0] = es; s_red[wid][1] = S01; s_red[wid][2] = S02; }
    __syncthreads();
    if (tid == 0) {
        float a = 0.f, c = 0.f, e = 0.f;
        for (int w = 0; w < 12; w++) { a += s_red[w][0]; c += s_red[w][1]; e += s_red[w][2]; }
        float inv0 = 1.0f / (a + (float)s0 * expf(tanhf(ckq0)));
        s_b[0] = inv0;
        s_b[1] = inv0 * c;
        s_b[2] = inv0 * e;
    }
    __syncthreads();
    float inv0 = s_b[0];
    float q1 = s_b[1] + db1 + g_cc1;

    // hop 1
    float ckq1 = g_ck + q1;
    es = 0.f; S01 = 0.f;
    for (int s = s0 + tid; s < SS; s += NT) {
        float w = 1.0f - (float)(s - s0) * invlen;
        float e = expf(tanhf(w * s_sv[s] + ckq1));
        float ew = e * w;
        s_c1[s] = ew;
        es += e; S01 += ew * s_t1[s];
    }
#pragma unroll
    for (int o = 16; o; o >>= 1) {
        es  += __shfl_xor_sync(0xffffffffu, es, o);
        S01 += __shfl_xor_sync(0xffffffffu, S01, o);
    }
    if (lane == 0) { s_red[wid][0] = es; s_red[wid][1] = S01; }
    __syncthreads();
    if (tid == 0) {
        float a = 0.f, c = 0.f;
        for (int w = 0; w < 12; w++) { a += s_red[w][0]; c += s_red[w][1]; }
        float inv1 = 1.0f / (a + (float)s0 * expf(tanhf(ckq1)));
        s_b[3] = inv1;
        s_b[4] = inv1 * c;
    }
    __syncthreads();
    float inv1 = s_b[3];
    float q2 = s_b[4] + s_b[2] + db2 + g_cc2;

    // hop 2
    float ckq2 = g_ck + q2;
    es = 0.f;
    for (int s = s0 + tid; s < SS; s += NT) {
        float w = 1.0f - (float)(s - s0) * invlen;
        float e = expf(tanhf(w * s_sv[s] + ckq2));
        s_c2[s] = e * w;
        es += e;
    }
#pragma unroll
    for (int o = 16; o; o >>= 1) es += __shfl_xor_sync(0xffffffffu, es, o);
    if (lane == 0) s_red[wid][0] = es;
    __syncthreads();
    if (tid == 0) {
        float a = 0.f;
        for (int w = 0; w < 12; w++) a += s_red[w][0];
        s_b[5] = 1.0f / (a + (float)s0 * expf(tanhf(ckq2)));
    }
    __syncthreads();
    float inv2 = s_b[5];

    for (int s = s0 + tid; s < SS; s += NT) {
        s_c0[s] *= inv0; s_c1[s] *= inv1; s_c2[s] *= inv2;
    }
    __syncthreads();

    // single shared gather: am0, am1, am2
    if (tid < 300) {
        int grp = tid / D4;
        int ch = tid - grp * D4;
        float4 a0 = make_float4(0.f, 0.f, 0.f, 0.f);
        float4 a1 = make_float4(0.f, 0.f, 0.f, 0.f);
        float4 a2 = make_float4(0.f, 0.f, 0.f, 0.f);
        int s = s0 + grp;
        for (; s + 28 < SS; s += 32) {
            int ix[8]; float c0[8], c1[8], c2[8];
#pragma unroll
            for (int j = 0; j < 8; j++) {
                int ss = s + 4 * j;
                ix[j] = s_idx[ss]; c0[j] = s_c0[ss]; c1[j] = s_c1[ss]; c2[j] = s_c2[ss];
            }
            uint2 v[8];
#pragma unroll
            for (int j = 0; j < 8; j++) v[j] = g_embh[(size_t)ix[j] * D4 + ch];
#pragma unroll
            for (int j = 0; j < 8; j++) {
                float2 lo = __half22float2(*reinterpret_cast<__half2*>(&v[j].x));
                float2 hi = __half22float2(*reinterpret_cast<__half2*>(&v[j].y));
                a0.x += c0[j] * lo.x; a0.y += c0[j] * lo.y; a0.z += c0[j] * hi.x; a0.w += c0[j] * hi.y;
                a1.x += c1[j] * lo.x; a1.y += c1[j] * lo.y; a1.z += c1[j] * hi.x; a1.w += c1[j] * hi.y;
                a2.x += c2[j] * lo.x; a2.y += c2[j] * lo.y; a2.z += c2[j] * hi.x; a2.w += c2[j] * hi.y;
            }
        }
        for (; s < SS; s += 4) {
            float c0 = s_c0[s], c1 = s_c1[s], c2 = s_c2[s];
            uint2 v = g_embh[(size_t)s_idx[s] * D4 + ch];
            float2 lo = __half22float2(*reinterpret_cast<__half2*>(&v.x));
            float2 hi = __half22float2(*reinterpret_cast<__half2*>(&v.y));
            a0.x += c0 * lo.x; a0.y += c0 * lo.y; a0.z += c0 * hi.x; a0.w += c0 * hi.y;
            a1.x += c1 * lo.x; a1.y += c1 * lo.y; a1.z += c1 * hi.x; a1.w += c1 * hi.y;
            a2.x += c2 * lo.x; a2.y += c2 * lo.y; a2.z += c2 * hi.x; a2.w += c2 * hi.y;
        }
        s_part[0][grp][ch] = a0;
        s_part[1][grp][ch] = a1;
        s_part[2][grp][ch] = a2;
    }
    __syncthreads();
    if (tid < 225) {
        int a = tid / D4, ch = tid - a * D4;
        float4 g0 = s_part[a][0][ch], g1 = s_part[a][1][ch];
        float4 g2 = s_part[a][2][ch], g3 = s_part[a][3][ch];
        float4 r;
        r.x = (g0.x + g1.x) + (g2.x + g3.x);
        r.y = (g0.y + g1.y) + (g2.y + g3.y);
        r.z = (g0.z + g1.z) + (g2.z + g3.z);
        r.w = (g0.w + g1.w) + (g2.w + g3.w);
        reinterpret_cast<float4*>(s_am[a])[ch] = r;
    }
    __syncthreads();

    // output: out[b] = M2.am2 + M1.am1 + M0.am0 + Mx.x0 + cvec
    {
        int p = wid >> 2, src = wid & 3;
        const float* M = (src == 0) ? (pM2 + p * DD) : (src == 1) ? (pM1 + p * DD)
                       : (src == 2) ? (pM0 + p * DD) : (pMX + p * DD);
        const float* vec = (src == 0) ? s_am[2] : (src == 1) ? s_am[1]
                         : (src == 2) ? s_am[0] : s_x0;
        float acc = 0.f;
        for (int d = lane; d < DD; d += 32) acc += M[d] * vec[d];
#pragma unroll
        for (int o = 16; o; o >>= 1) acc += __shfl_xor_sync(0xffffffffu, acc, o);
        if (lane == 0) s_red[wid][0] = acc;
    }
    __syncthreads();
    if (tid < PP) {
        out[b * PP + tid] = pCV[tid] + (s_red[tid * 4][0] + s_red[tid * 4 + 1][0])
                                     + (s_red[tid * 4 + 2][0] + s_red[tid * 4 + 3][0]);
    }
}

// ---------------- launch -----------------
extern "C" void kernel_launch(void* const* d_in, const int* in_sizes, int n_in,
                              void* d_out, int out_size) {
    const int*   text = (const int*)d_in[0];
    const int*   asp  = (const int*)d_in[1];
    const float* emb  = (const float*)d_in[2];
    const float* Wx   = (const float*)d_in[3];
    const float* bx   = (const float*)d_in[4];
    const float* Wk   = (const float*)d_in[5];
    const float* bk   = (const float*)d_in[6];
    const float* Wq   = (const float*)d_in[7];
    const float* bq   = (const float*)d_in[8];
    const float* wmlp = (const float*)d_in[9];
    const float* Wp   = (const float*)d_in[10];
    const float* bp   = (const float*)d_in[11];
    const float* Wd   = (const float*)d_in[12];
    const float* bd   = (const float*)d_in[13];
    float* out = (float*)d_out;

    k_prep<<<NCHAIN, 320>>>(Wq, Wk, Wp, Wx, Wd, wmlp, bk, bq, bp, bx, bd);
    k_vocab<<<(VV + 3) / 4, 128>>>(emb);
    k_mega<<<BB, 384>>>(text, asp, out);
}

// round 10
// speedup vs baseline: 3.3319x; 1.0312x over previous
#include <cuda_runtime.h>
#include <cuda_fp16.h>
#include <math.h>

#define BB 512
#define SS 512
#define VV 50000
#define DD 300
#define PP 3
#define D4 75   // DD/4
#define CE 30   // e per chunk
#define NBLK 256
#define NPREP 71
#define NT 384

// ---------------- accumulator block (zeroed in-kernel) ----------------
#define ACCN 11104
__device__ __align__(16) float g_acc[ACCN];
#define pU   (g_acc + 0)
#define pV   (g_acc + 300)
#define pU2  (g_acc + 600)
#define pB1  (g_acc + 900)
#define pB2  (g_acc + 1200)
#define pP1  (g_acc + 1500)
#define pP2  (g_acc + 1800)
#define pA1  (g_acc + 2100)
#define pA2  (g_acc + 2400)
#define pBCV (g_acc + 2700)
#define pG   (g_acc + 3000)
#define pE   (g_acc + 3900)
#define pH   (g_acc + 4800)
#define pF   (g_acc + 5700)
#define pJ   (g_acc + 6600)
#define pM2  (g_acc + 7500)
#define pM1  (g_acc + 8400)
#define pM0  (g_acc + 9300)
#define pMX  (g_acc + 10200)
#define pCV  (g_acc + 11100)

__device__ float g_ck, g_cq, g_c2, g_cc1, g_cc2;
__device__ __align__(16) float4 g_svt[VV];              // {sv, t1, t2, 0}
__device__ __align__(16) uint2 g_embh[(size_t)VV * D4]; // fp16 emb shadow

// ---------------- replay-safe grid barrier (variable participant count) -----
__device__ volatile unsigned g_barphase[8];
__device__ unsigned g_barcnt[8];

__device__ __forceinline__ void gridbar(int slot, unsigned count) {
    __syncthreads();
    if (threadIdx.x == 0) {
        __threadfence();
        unsigned ph = g_barphase[slot];
        unsigned t = atomicAdd(&g_barcnt[slot], 1u);
        if (t == count - 1) {
            g_barcnt[slot] = 0;            // reset for next replay
            __threadfence();
            atomicAdd((unsigned*)&g_barphase[slot], 1u);
        } else {
            while (g_barphase[slot] == ph) { __nanosleep(32); }
        }
        __threadfence();
    }
    __syncthreads();
}

// ---------------- device helpers ----------------
__device__ __forceinline__ float lanedot(const float* __restrict__ a,
                                         const float* __restrict__ b, int lane) {
    float s = 0.f;
    for (int e = lane; e < DD; e += 32) s += a[e] * b[e];
#pragma unroll
    for (int o = 16; o; o >>= 1) s += __shfl_xor_sync(0xffffffffu, s, o);
    return s;
}

// out[f] += sum_{e in chunk} M[e*DD+f] * y[e]
__device__ __forceinline__ void mv_part(const float* __restrict__ M,
                                        const float* __restrict__ y,
                                        float* __restrict__ out, int chunk) {
    __shared__ float sy[CE];
    int t = threadIdx.x;
    if (t < CE) sy[t] = y[chunk * CE + t];
    __syncthreads();
    if (t < DD) {
        float acc = 0.f;
        const float* Mp = M + chunk * CE * DD + t;
#pragma unroll
        for (int e = 0; e < CE; e++) acc += Mp[e * DD] * sy[e];
        atomicAdd(out + t, acc);
    }
    __syncthreads();
}

// out[p][f] += sum_{e in chunk} A[p*DD+e] * B[e*DD+f]  for p=0..2
__device__ __forceinline__ void mm3_part(const float* __restrict__ A,
                                         const float* __restrict__ B,
                                         float* __restrict__ out, int chunk) {
    __shared__ float sa[3][CE];
    int t = threadIdx.x;
    if (t < 3 * CE) sa[t / CE][t % CE] = A[(t / CE) * DD + chunk * CE + (t % CE)];
    __syncthreads();
    if (t < DD) {
        float a0 = 0.f, a1 = 0.f, a2 = 0.f;
        const float* Bp = B + chunk * CE * DD + t;
#pragma unroll
        for (int e = 0; e < CE; e++) {
            float b = Bp[e * DD];
            a0 += sa[0][e] * b; a1 += sa[1][e] * b; a2 += sa[2][e] * b;
        }
        atomicAdd(out + t, a0);
        atomicAdd(out + DD + t, a1);
        atomicAdd(out + 2 * DD + t, a2);
    }
    __syncthreads();
}

// ============================================================
// ONE persistent kernel: prep chain || shadow build, then svt, then mega.
// ============================================================
__global__ __launch_bounds__(NT, 2) void k_all(
        const float* __restrict__ Wq, const float* __restrict__ Wk,
        const float* __restrict__ Wp, const float* __restrict__ Wx,
        const float* __restrict__ Wd, const float* __restrict__ wmlp,
        const float* __restrict__ bk, const float* __restrict__ bq,
        const float* __restrict__ bp, const float* __restrict__ bx,
        const float* __restrict__ bd, const float* __restrict__ emb,
        const int* __restrict__ text, const int* __restrict__ asp,
        float* __restrict__ out) {
    int b = blockIdx.x, tid = threadIdx.x;
    int lane = tid & 31, wid = tid >> 5;

    // shared memory
    __shared__ int   s_idx[SS];
    __shared__ int   s_asp[8];
    __shared__ int   s_len;
    __shared__ float s_sv[SS], s_t1[SS], s_t2[SS];
    __shared__ float s_c0[SS], s_c1[SS], s_c2[SS];
    __shared__ __align__(16) float s_x0[DD];
    __shared__ __align__(16) float4 s_part[3][4][D4];
    __shared__ __align__(16) float s_am[3][DD];
    __shared__ float s_red[12][3];
    __shared__ float s_b[6];
    __shared__ __align__(16) float4 sV[D4], sA1[D4], sA2[D4];

    // ================= phase A: prep chain (blocks < NPREP) or shadow =======
    if (b < NPREP) {
        // zero accumulators
        for (int i = b * NT + tid; i < ACCN; i += NPREP * NT) g_acc[i] = 0.f;
        gridbar(0, NPREP);

        // level 1
        if (b < 10) {
            mv_part(Wq, wmlp + DD, pU, b);
        } else if (b < 20) {
            mv_part(Wk, wmlp, pV, b - 10);
        } else if (b < 30) {
            mm3_part(Wd, Wp, pG, b - 20);
        } else if (b < 40) {
            mm3_part(Wd, Wx, pE, b - 30);
        } else if (b < 70) {
            if (wid < 10) {
                int row = (b - 40) * 10 + wid;
                float s = lanedot(Wp + row * DD, bk, lane);
                if (lane == 0) pBCV[row] = s + bp[row] + bx[row];
            }
        } else {
            if (wid == 0) { float s = lanedot(bk, wmlp, lane); if (lane == 0) g_ck = s; }
            if (wid == 1) { float s = lanedot(bq, wmlp + DD, lane); if (lane == 0) g_cq = s; }
        }
        gridbar(1, NPREP);

        // level 2
        if (b < 10) {
            mv_part(Wx, pU, pU2, b);
        } else if (b < 20) {
            mm3_part(pG, Wk, pM2, b - 10);
        } else if (b < 30) {
            mm3_part(pE, Wp, pH, b - 20);
        } else if (b < 40) {
            mm3_part(pE, Wx, pF, b - 30);
        } else if (b == 40) {
            if (wid == 0) { float s = lanedot(bx, pU, lane); if (lane == 0) g_c2 = s + g_cq; }
        }
        gridbar(2, NPREP);

        // level 3
        if (b < 10) {
            mv_part(Wx, pU2, pB1, b);
        } else if (b < 20) {
            mv_part(Wp, pU2, pP1, b - 10);
        } else if (b < 30) {
            mm3_part(pH, Wk, pM1, b - 20);
        } else if (b < 40) {
            mm3_part(pF, Wx, pMX, b - 30);
        } else if (b < 50) {
            mm3_part(pF, Wp, pJ, b - 40);
        } else if (b == 50) {
            if (wid == 0) { float s = lanedot(pBCV, pU2, lane); if (lane == 0) g_cc1 = s + g_c2; }
            if (wid >= 1 && wid <= 3) {
                int p = wid - 1;
                float s = 0.f;
                for (int e = lane; e < DD; e += 32)
                    s += (Wd[p * DD + e] + pE[p * DD + e] + pF[p * DD + e]) * pBCV[e];
#pragma unroll
                for (int o = 16; o; o >>= 1) s += __shfl_xor_sync(0xffffffffu, s, o);
                if (lane == 0) pCV[p] = s + bd[p];
            }
        }
        gridbar(3, NPREP);

        // level 4
        if (b < 10) {
            mv_part(Wk, pP1, pA1, b);
        } else if (b < 20) {
            mv_part(Wx, pB1, pB2, b - 10);
        } else if (b < 30) {
            mv_part(Wp, pB1, pP2, b - 20);
        } else if (b < 40) {
            mm3_part(pJ, Wk, pM0, b - 30);
        } else if (b == 40) {
            if (wid == 0) { float s = lanedot(pBCV, pB1, lane); if (lane == 0) g_cc2 = s + g_cc1; }
        }
        gridbar(4, NPREP);

        // level 5
        if (b < 10) mv_part(Wk, pP2, pA2, b);
    } else {
        // ---- fp16 shadow: flat coalesced convert, manual x4 MLP ----
        const int TOT = VV * D4;
        const int NSH = (NBLK - NPREP) * NT;
        const float4* em4 = reinterpret_cast<const float4*>(emb);
        int c = (b - NPREP) * NT + tid;
        for (; c + 3 * NSH < TOT; c += 4 * NSH) {
            float4 e0 = em4[c], e1 = em4[c + NSH], e2 = em4[c + 2 * NSH], e3 = em4[c + 3 * NSH];
            uint2 u0, u1, u2, u3;
            __half2 h;
            h = __floats2half2_rn(e0.x, e0.y); u0.x = *reinterpret_cast<unsigned*>(&h);
            h = __floats2half2_rn(e0.z, e0.w); u0.y = *reinterpret_cast<unsigned*>(&h);
            h = __floats2half2_rn(e1.x, e1.y); u1.x = *reinterpret_cast<unsigned*>(&h);
            h = __floats2half2_rn(e1.z, e1.w); u1.y = *reinterpret_cast<unsigned*>(&h);
            h = __floats2half2_rn(e2.x, e2.y); u2.x = *reinterpret_cast<unsigned*>(&h);
            h = __floats2half2_rn(e2.z, e2.w); u2.y = *reinterpret_cast<unsigned*>(&h);
            h = __floats2half2_rn(e3.x, e3.y); u3.x = *reinterpret_cast<unsigned*>(&h);
            h = __floats2half2_rn(e3.z, e3.w); u3.y = *reinterpret_cast<unsigned*>(&h);
            g_embh[c] = u0; g_embh[c + NSH] = u1;
            g_embh[c + 2 * NSH] = u2; g_embh[c + 3 * NSH] = u3;
        }
        for (; c < TOT; c += NSH) {
            float4 e = em4[c];
            uint2 u; __half2 h;
            h = __floats2half2_rn(e.x, e.y); u.x = *reinterpret_cast<unsigned*>(&h);
            h = __floats2half2_rn(e.z, e.w); u.y = *reinterpret_cast<unsigned*>(&h);
            g_embh[c] = u;
        }
    }
    gridbar(5, NBLK);

    // ================= phase B: svt from fp16 shadow ========================
    if (tid < D4) {
        sV[tid]  = reinterpret_cast<const float4*>(pV)[tid];
        sA1[tid] = reinterpret_cast<const float4*>(pA1)[tid];
        sA2[tid] = reinterpret_cast<const float4*>(pA2)[tid];
    }
    __syncthreads();
    for (int row = b * 12 + wid; row < VV; row += NBLK * 12) {
        const uint2* er = g_embh + (size_t)row * D4;
        float av = 0.f, a1 = 0.f, a2 = 0.f;
#pragma unroll
        for (int i = lane; i < D4; i += 32) {
            uint2 u = er[i];
            float2 lo = __half22float2(*reinterpret_cast<__half2*>(&u.x));
            float2 hi = __half22float2(*reinterpret_cast<__half2*>(&u.y));
            float4 vv = sV[i], w1 = sA1[i], w2 = sA2[i];
            av += lo.x * vv.x + lo.y * vv.y + hi.x * vv.z + hi.y * vv.w;
            a1 += lo.x * w1.x + lo.y * w1.y + hi.x * w1.z + hi.y * w1.w;
            a2 += lo.x * w2.x + lo.y * w2.y + hi.x * w2.z + hi.y * w2.w;
        }
#pragma unroll
        for (int o = 16; o; o >>= 1) {
            av += __shfl_xor_sync(0xffffffffu, av, o);
            a1 += __shfl_xor_sync(0xffffffffu, a1, o);
            a2 += __shfl_xor_sync(0xffffffffu, a2, o);
        }
        if (lane == 0) g_svt[row] = make_float4(av, a1, a2, 0.f);
    }
    gridbar(6, NBLK);

    // ================= phase C: mega, 2 rows per block ======================
    for (int row = b; row < BB; row += NBLK) {
        if (tid < 8) s_asp[tid] = asp[row * 8 + tid];
        int cnt = 0;
        for (int s = tid; s < SS; s += NT) {
            int ix = text[row * SS + s];
            s_idx[s] = ix;
            cnt += (ix != 0);
            float4 svt = g_svt[ix];
            s_sv[s] = svt.x; s_t1[s] = svt.y; s_t2[s] = svt.z;
        }
#pragma unroll
        for (int o = 16; o; o >>= 1) cnt += __shfl_xor_sync(0xffffffffu, cnt, o);
        if (lane == 0) s_red[wid][0] = (float)cnt;
        __syncthreads();
        if (tid == 0) {
            float a = 0.f;
            for (int w = 0; w < 12; w++) a += s_red[w][0];
            s_len = (int)a;
        }
        // x0 from fp16 shadow
        if (tid < D4) {
            int na = 0;
#pragma unroll
            for (int j = 0; j < 8; j++) na += (s_asp[j] != 0);
            float invn = 1.0f / (float)na;
            float4 acc = make_float4(0.f, 0.f, 0.f, 0.f);
#pragma unroll
            for (int j = 0; j < 8; j++) {
                uint2 v = g_embh[(size_t)s_asp[j] * D4 + tid];   // row 0 is zeros
                float2 lo = __half22float2(*reinterpret_cast<__half2*>(&v.x));
                float2 hi = __half22float2(*reinterpret_cast<__half2*>(&v.y));
                acc.x += lo.x; acc.y += lo.y; acc.z += hi.x; acc.w += hi.y;
            }
            acc.x *= invn; acc.y *= invn; acc.z *= invn; acc.w *= invn;
            reinterpret_cast<float4*>(s_x0)[tid] = acc;
        }
        __syncthreads();

        float d0 = 0.f, d1 = 0.f, d2 = 0.f;
        if (tid < DD) {
            float xv = s_x0[tid];
            d0 = xv * pU2[tid]; d1 = xv * pB1[tid]; d2 = xv * pB2[tid];
        }
#pragma unroll
        for (int o = 16; o; o >>= 1) {
            d0 += __shfl_xor_sync(0xffffffffu, d0, o);
            d1 += __shfl_xor_sync(0xffffffffu, d1, o);
            d2 += __shfl_xor_sync(0xffffffffu, d2, o);
        }
        if (lane == 0) { s_red[wid][0] = d0; s_red[wid][1] = d1; s_red[wid][2] = d2; }
        __syncthreads();
        if (tid == 0) {
            float a = 0.f, c = 0.f, e = 0.f;
            for (int w = 0; w < 12; w++) { a += s_red[w][0]; c += s_red[w][1]; e += s_red[w][2]; }
            s_b[0] = a; s_b[1] = c; s_b[2] = e;
        }
        __syncthreads();
        float du2 = s_b[0], db1 = s_b[1], db2 = s_b[2];

        int len = s_len;
        int s0 = SS - len;
        float invlen = 1.0f / (float)len;

        // hop 0
        float ckq0 = g_ck + du2 + g_c2;
        float es = 0.f, S01 = 0.f, S02 = 0.f;
        for (int s = s0 + tid; s < SS; s += NT) {
            float w = 1.0f - (float)(s - s0) * invlen;
            float e = expf(tanhf(w * s_sv[s] + ckq0));
            float ew = e * w;
            s_c0[s] = ew;
            es += e; S01 += ew * s_t1[s]; S02 += ew * s_t2[s];
        }
#pragma unroll
        for (int o = 16; o; o >>= 1) {
            es  += __shfl_xor_sync(0xffffffffu, es, o);
            S01 += __shfl_xor_sync(0xffffffffu, S01, o);
            S02 += __shfl_xor_sync(0xffffffffu, S02, o);
        }
        if (lane == 0) { s_red[wid][0] = es; s_red[wid][1] = S01; s_red[wid][2] = S02; }
        __syncthreads();
        if (tid == 0) {
            float a = 0.f, c = 0.f, e = 0.f;
            for (int w = 0; w < 12; w++) { a += s_red[w][0]; c += s_red[w][1]; e += s_red[w][2]; }
            float inv0 = 1.0f / (a + (float)s0 * expf(tanhf(ckq0)));
            s_b[0] = inv0;
            s_b[1] = inv0 * c;
            s_b[2] = inv0 * e;
        }
        __syncthreads();
        float inv0 = s_b[0];
        float q1 = s_b[1] + db1 + g_cc1;

        // hop 1
        float ckq1 = g_ck + q1;
        es = 0.f; S01 = 0.f;
        for (int s = s0 + tid; s < SS; s += NT) {
            float w = 1.0f - (float)(s - s0) * invlen;
            float e = expf(tanhf(w * s_sv[s] + ckq1));
            float ew = e * w;
            s_c1[s] = ew;
            es += e; S01 += ew * s_t1[s];
        }
#pragma unroll
        for (int o = 16; o; o >>= 1) {
            es  += __shfl_xor_sync(0xffffffffu, es, o);
            S01 += __shfl_xor_sync(0xffffffffu, S01, o);
        }
        if (lane == 0) { s_red[wid][0] = es; s_red[wid][1] = S01; }
        __syncthreads();
        if (tid == 0) {
            float a = 0.f, c = 0.f;
            for (int w = 0; w < 12; w++) { a += s_red[w][0]; c += s_red[w][1]; }
            float inv1 = 1.0f / (a + (float)s0 * expf(tanhf(ckq1)));
            s_b[3] = inv1;
            s_b[4] = inv1 * c;
        }
        __syncthreads();
        float inv1 = s_b[3];
        float q2 = s_b[4] + s_b[2] + db2 + g_cc2;

        // hop 2
        float ckq2 = g_ck + q2;
        es = 0.f;
        for (int s = s0 + tid; s < SS; s += NT) {
            float w = 1.0f - (float)(s - s0) * invlen;
            float e = expf(tanhf(w * s_sv[s] + ckq2));
            s_c2[s] = e * w;
            es += e;
        }
#pragma unroll
        for (int o = 16; o; o >>= 1) es += __shfl_xor_sync(0xffffffffu, es, o);
        if (lane == 0) s_red[wid][0] = es;
        __syncthreads();
        if (tid == 0) {
            float a = 0.f;
            for (int w = 0; w < 12; w++) a += s_red[w][0];
            s_b[5] = 1.0f / (a + (float)s0 * expf(tanhf(ckq2)));
        }
        __syncthreads();
        float inv2 = s_b[5];

        for (int s = s0 + tid; s < SS; s += NT) {
            s_c0[s] *= inv0; s_c1[s] *= inv1; s_c2[s] *= inv2;
        }
        __syncthreads();

        // single shared gather: am0, am1, am2
        if (tid < 300) {
            int grp = tid / D4;
            int ch = tid - grp * D4;
            float4 a0 = make_float4(0.f, 0.f, 0.f, 0.f);
            float4 a1 = make_float4(0.f, 0.f, 0.f, 0.f);
            float4 a2 = make_float4(0.f, 0.f, 0.f, 0.f);
            int s = s0 + grp;
            for (; s + 28 < SS; s += 32) {
                int ix[8]; float c0[8], c1[8], c2[8];
#pragma unroll
                for (int j = 0; j < 8; j++) {
                    int ss = s + 4 * j;
                    ix[j] = s_idx[ss]; c0[j] = s_c0[ss]; c1[j] = s_c1[ss]; c2[j] = s_c2[ss];
                }
                uint2 v[8];
#pragma unroll
                for (int j = 0; j < 8; j++) v[j] = g_embh[(size_t)ix[j] * D4 + ch];
#pragma unroll
                for (int j = 0; j < 8; j++) {
                    float2 lo = __half22float2(*reinterpret_cast<__half2*>(&v[j].x));
                    float2 hi = __half22float2(*reinterpret_cast<__half2*>(&v[j].y));
                    a0.x += c0[j] * lo.x; a0.y += c0[j] * lo.y; a0.z += c0[j] * hi.x; a0.w += c0[j] * hi.y;
                    a1.x += c1[j] * lo.x; a1.y += c1[j] * lo.y; a1.z += c1[j] * hi.x; a1.w += c1[j] * hi.y;
                    a2.x += c2[j] * lo.x; a2.y += c2[j] * lo.y; a2.z += c2[j] * hi.x; a2.w += c2[j] * hi.y;
                }
            }
            for (; s < SS; s += 4) {
                float c0 = s_c0[s], c1 = s_c1[s], c2 = s_c2[s];
                uint2 v = g_embh[(size_t)s_idx[s] * D4 + ch];
                float2 lo = __half22float2(*reinterpret_cast<__half2*>(&v.x));
                float2 hi = __half22float2(*reinterpret_cast<__half2*>(&v.y));
                a0.x += c0 * lo.x; a0.y += c0 * lo.y; a0.z += c0 * hi.x; a0.w += c0 * hi.y;
                a1.x += c1 * lo.x; a1.y += c1 * lo.y; a1.z += c1 * hi.x; a1.w += c1 * hi.y;
                a2.x += c2 * lo.x; a2.y += c2 * lo.y; a2.z += c2 * hi.x; a2.w += c2 * hi.y;
            }
            s_part[0][grp][ch] = a0;
            s_part[1][grp][ch] = a1;
            s_part[2][grp][ch] = a2;
        }
        __syncthreads();
        if (tid < 225) {
            int a = tid / D4, ch = tid - a * D4;
            float4 g0 = s_part[a][0][ch], g1 = s_part[a][1][ch];
            float4 g2 = s_part[a][2][ch], g3 = s_part[a][3][ch];
            float4 r;
            r.x = (g0.x + g1.x) + (g2.x + g3.x);
            r.y = (g0.y + g1.y) + (g2.y + g3.y);
            r.z = (g0.z + g1.z) + (g2.z + g3.z);
            r.w = (g0.w + g1.w) + (g2.w + g3.w);
            reinterpret_cast<float4*>(s_am[a])[ch] = r;
        }
        __syncthreads();

        // output: out[row] = M2.am2 + M1.am1 + M0.am0 + Mx.x0 + cvec
        {
            int p = wid >> 2, src = wid & 3;
            const float* M = (src == 0) ? (pM2 + p * DD) : (src == 1) ? (pM1 + p * DD)
                           : (src == 2) ? (pM0 + p * DD) : (pMX + p * DD);
            const float* vec = (src == 0) ? s_am[2] : (src == 1) ? s_am[1]
                             : (src == 2) ? s_am[0] : s_x0;
            float acc = 0.f;
            for (int d = lane; d < DD; d += 32) acc += M[d] * vec[d];
#pragma unroll
            for (int o = 16; o; o >>= 1) acc += __shfl_xor_sync(0xffffffffu, acc, o);
            if (lane == 0) s_red[wid][0] = acc;
        }
        __syncthreads();
        if (tid < PP) {
            out[row * PP + tid] = pCV[tid] + (s_red[tid * 4][0] + s_red[tid * 4 + 1][0])
                                           + (s_red[tid * 4 + 2][0] + s_red[tid * 4 + 3][0]);
        }
        __syncthreads();
    }
}

// ---------------- launch -----------------
extern "C" void kernel_launch(void* const* d_in, const int* in_sizes, int n_in,
                              void* d_out, int out_size) {
    const int*   text = (const int*)d_in[0];
    const int*   asp  = (const int*)d_in[1];
    const float* emb  = (const float*)d_in[2];
    const float* Wx   = (const float*)d_in[3];
    const float* bx   = (const float*)d_in[4];
    const float* Wk   = (const float*)d_in[5];
    const float* bk   = (const float*)d_in[6];
    const float* Wq   = (const float*)d_in[7];
    const float* bq   = (const float*)d_in[8];
    const float* wmlp = (const float*)d_in[9];
    const float* Wp   = (const float*)d_in[10];
    const float* bp   = (const float*)d_in[11];
    const float* Wd   = (const float*)d_in[12];
    const float* bd   = (const float*)d_in[13];
    float* out = (float*)d_out;

    k_all<<<NBLK, NT>>>(Wq, Wk, Wp, Wx, Wd, wmlp, bk, bq, bp, bx, bd,
                        emb, text, asp, out);
}